// round 8
// baseline (speedup 1.0000x reference)
#include <cuda_runtime.h>
#include <math.h>
#include <stdint.h>

typedef unsigned long long ull;

#define H_DIM 64
#define W_DIM 64
#define B_DIM 64
#define R_DIM 128
#define D2    256
#define LPOS  (63*63)

// scratch (device globals; no runtime allocation)
__device__ float g_S[(size_t)H_DIM * W_DIM * B_DIM * R_DIM];  // [cell][b][r]
__device__ float g_A[(size_t)B_DIM * D2 * D2];
__device__ float g_y[(size_t)B_DIM * D2];

// ---------------------------------------------------------------------------
// packed fp32x2 + cluster helpers
// ---------------------------------------------------------------------------
__device__ __forceinline__ ull ffma2(ull a, ull b, ull c)
{
    ull d;
    asm("fma.rn.f32x2 %0, %1, %2, %3;" : "=l"(d) : "l"(a), "l"(b), "l"(c));
    return d;
}
__device__ __forceinline__ ull fadd2(ull a, ull b)
{
    ull d;
    asm("add.rn.f32x2 %0, %1, %2;" : "=l"(d) : "l"(a), "l"(b));
    return d;
}
__device__ __forceinline__ float2 unpack2(ull v)
{
    float2 r;
    asm("mov.b64 {%0, %1}, %2;" : "=f"(r.x), "=f"(r.y) : "l"(v));
    return r;
}
__device__ __forceinline__ ull pack2(float a, float b)
{
    ull d;
    asm("mov.b64 %0, {%1, %2};" : "=l"(d) : "f"(a), "f"(b));
    return d;
}
__device__ __forceinline__ uint32_t smem_u32(const void* p)
{
    uint32_t a;
    asm("{ .reg .u64 t; cvta.to.shared.u64 t, %1; cvt.u32.u64 %0, t; }"
        : "=r"(a) : "l"(p));
    return a;
}
__device__ __forceinline__ void st_cluster_b32(uint32_t addr, float v)
{
    asm volatile("st.shared::cluster.b32 [%0], %1;" :: "r"(addr), "f"(v) : "memory");
}
#define CLUSTER_SYNC() do { \
    asm volatile("barrier.cluster.arrive.aligned;" ::: "memory"); \
    asm volatile("barrier.cluster.wait.aligned;"   ::: "memory"); \
} while (0)

// ---------------------------------------------------------------------------
// Kernel 1: ESN recurrence.  2-CTA cluster per batch; CTA rank owns the
// r-half [rank*64, rank*64+64).  Wavefront over anti-diagonals, chunks of 16
// cells between barrier pairs.  1024 threads:
//   g  = t >> 7       : 8 k-groups of 32 k (g<4 -> W1/left, g>=4 -> W2/above)
//   subcell = (t>>6)&1: which of 2 cells handled per pass (8 passes/chunk)
//   r  = t & 63       : output unit within my half
// K-PACKED f32x2: each ffma2 multiplies (s_2k, s_2k+1) by (W[2k][r], W[2k+1][r]);
// lanes accumulate k-even/k-odd, summed in ph2.  Diagonal states are plain
// floats in two zero-initialized 65-slot ring buffers (no duplication);
// peer half arrives via st.shared::cluster, published by one cluster barrier
// per diagonal.  Per chunk: ph1 (all threads, 8 cells each: 4 LDS.128 +
// 16 FFMA2 + 1 STS per cell), BAR, ph2 (every thread one (cell,r) output:
// 8-way reduce + tanh + 3 stores), BAR.
// ---------------------------------------------------------------------------
#define CCH 16
#define ESN_BUF_FLOATS (65 * 128)
#define ESN_BUF_BYTES  (ESN_BUF_FLOATS * 4)                  // 33280
#define ESN_SMEM (2 * ESN_BUF_BYTES + CCH * 8 * 64 * 8)      // 66560 + 65536

__global__ __launch_bounds__(1024, 1) __cluster_dims__(2, 1, 1)
void esn_cluster(const float* __restrict__ x, const float* __restrict__ Win,
                 const float* __restrict__ W1, const float* __restrict__ W2)
{
    extern __shared__ float sm[];
    float* buf0 = sm;                          // [65][128] diag states
    float* buf1 = sm + ESN_BUF_FLOATS;
    ull*   red  = (ull*)(sm + 2 * ESN_BUF_FLOATS);   // [16][8][64]

    uint32_t rank;
    asm("mov.u32 %0, %%cluster_ctarank;" : "=r"(rank));
    const int b  = blockIdx.x >> 1;
    const int t  = threadIdx.x;
    const int g  = t >> 7;                     // 0..7
    const int subcell = (t >> 6) & 1;
    const int r  = t & 63;

    const int rbase = (int)(rank << 6);
    const int rcol  = rbase + r;
    const int kloc  = (g & 3) << 5;            // 0,32,64,96 within the matrix

    // one-time: 16 k-pair weight columns into registers
    const float* Wsrc = (g < 4) ? W1 : W2;
    ull wreg[16];
#pragma unroll
    for (int j = 0; j < 16; j++) {
        const int k = kloc + 2 * j;
        wreg[j] = pack2(Wsrc[k * R_DIM + rcol], Wsrc[(k + 1) * R_DIM + rcol]);
    }
    const float winr = Win[rcol];
    const float* xb = x + ((size_t)b << 12);

    const uint32_t my_base = smem_u32(sm);
    uint32_t peer_base;
    asm("mapa.shared::cluster.u32 %0, %1, %2;"
        : "=r"(peer_base) : "r"(my_base), "r"(rank ^ 1u));

    // zero both diagonal buffers (zero slots double as boundary guards)
    {
        float4* z = (float4*)sm;
        for (int u = t; u < (2 * ESN_BUF_FLOATS) / 4; u += 1024)
            z[u] = make_float4(0.f, 0.f, 0.f, 0.f);
    }
    __syncthreads();
    CLUSTER_SYNC();   // peer zeroing done before our DSMEM stores can land

    for (int d = 0; d < H_DIM + W_DIM - 1; d++) {
        const int hmin = (d > 63) ? d - 63 : 0;
        const int hmax = (d < 63) ? d : 63;
        float* prev = (d & 1) ? buf0 : buf1;
        float* cur  = (d & 1) ? buf1 : buf0;
        const uint32_t cur_off = (d & 1) ? (uint32_t)ESN_BUF_BYTES : 0u;

        for (int c0 = hmin; c0 <= hmax; c0 += CCH) {
            const int nc = (hmax - c0 + 1 < CCH) ? (hmax - c0 + 1) : CCH;

            // ---- phase 1: k-packed partial dot products ----
#pragma unroll 2
            for (int pass = 0; pass < 8; pass++) {
                const int ci = (pass << 1) | subcell;
                if (ci >= nc) continue;
                const int h = c0 + ci;
                // left slot(h)=h+1 ; above slot(h-1)=h ; unwritten slots = 0
                const int slot = (g < 4) ? (h + 1) : h;
                const ulonglong2* src =
                    (const ulonglong2*)(prev + slot * 128 + kloc);
                ull a0 = 0ull, a1 = 0ull;
#pragma unroll
                for (int i = 0; i < 8; i++) {
                    const ulonglong2 s = src[i];       // 2x (s_2k, s_2k+1)
                    a0 = ffma2(s.x, wreg[2 * i],     a0);
                    a1 = ffma2(s.y, wreg[2 * i + 1], a1);
                }
                red[((ci << 3) + g) * 64 + r] = fadd2(a0, a1);
            }
            __syncthreads();

            // ---- phase 2: one (cell, r) output per thread ----
            {
                const int ci = t >> 6;
                if (ci < nc) {
                    const int h = c0 + ci;
                    const int w = d - h;
                    const ull* rr = red + (ci << 9) + r;
                    ull s0 = rr[0],       s1 = rr[64];
                    ull s2 = rr[2 * 64],  s3 = rr[3 * 64];
                    s0 = fadd2(s0, rr[4 * 64]);
                    s1 = fadd2(s1, rr[5 * 64]);
                    s2 = fadd2(s2, rr[6 * 64]);
                    s3 = fadd2(s3, rr[7 * 64]);
                    const float2 v = unpack2(fadd2(fadd2(s0, s1), fadd2(s2, s3)));
                    const float xv = __ldg(xb + (h << 6) + w);
                    const float o = tanhf(fmaf(xv, winr, v.x + v.y));
                    const int idx = (h + 1) * 128 + rcol;
                    cur[idx] = o;
                    st_cluster_b32(peer_base + cur_off + (uint32_t)idx * 4u, o);
                    g_S[((size_t)(((h << 6) + w) << 6) + b) * R_DIM + rcol] = o;
                }
            }
            __syncthreads();
        }
        CLUSTER_SYNC();   // publish DSMEM half-states before next diagonal
    }
}

// ---------------------------------------------------------------------------
// Kernel 2: XtX, symmetric, f32x2.  grid = (10 tile-pairs, 64 batches).
// ---------------------------------------------------------------------------
__global__ __launch_bounds__(256) void xtx_kernel()
{
    const int b = blockIdx.y;
    const int p = blockIdx.x;
    const int ti = (p < 4) ? 0 : (p < 7) ? 1 : (p < 9) ? 2 : 3;
    const int tbase = (ti == 0) ? 0 : (ti == 1) ? 4 : (ti == 2) ? 7 : 9;
    const int tj = ti + (p - tbase);

    const int t = threadIdx.x;
    const int di0 = (t & 15) << 2;
    const int dj0 = (t >> 4) << 2;

    __shared__ float  sA [16][64];
    __shared__ float2 sBd[16][64];

    ull acc[2][4];
#pragma unroll
    for (int pp = 0; pp < 2; pp++)
#pragma unroll
        for (int j = 0; j < 4; j++) acc[pp][j] = 0ull;

    const int lr = t >> 4;
    const int qq = t & 15;

#pragma unroll 1
    for (int l0 = 0; l0 < LPOS; l0 += 16) {
        __syncthreads();
        const int l = l0 + lr;
        float4 va = make_float4(0.f, 0.f, 0.f, 0.f);
        float4 vb = make_float4(0.f, 0.f, 0.f, 0.f);
        if (l < LPOS) {
            const int i = l / 63;
            const int j = l - i * 63;
            {
                const int cell = (ti < 2) ? ((i + 1) * W_DIM + j) : (i * W_DIM + j + 1);
                const int off  = (ti & 1) << 6;
                va = *(const float4*)(g_S + (((size_t)cell << 6) + b) * R_DIM + off + (qq << 2));
            }
            {
                const int cell = (tj < 2) ? ((i + 1) * W_DIM + j) : (i * W_DIM + j + 1);
                const int off  = (tj & 1) << 6;
                vb = *(const float4*)(g_S + (((size_t)cell << 6) + b) * R_DIM + off + (qq << 2));
            }
        }
        *(float4*)&sA[lr][qq << 2] = va;
        sBd[lr][(qq << 2) + 0] = make_float2(vb.x, vb.x);
        sBd[lr][(qq << 2) + 1] = make_float2(vb.y, vb.y);
        sBd[lr][(qq << 2) + 2] = make_float2(vb.z, vb.z);
        sBd[lr][(qq << 2) + 3] = make_float2(vb.w, vb.w);
        __syncthreads();

#pragma unroll
        for (int l2 = 0; l2 < 16; l2++) {
            const ulonglong2 av  = *(const ulonglong2*)&sA[l2][di0];
            const ulonglong2 b01 = *(const ulonglong2*)&sBd[l2][dj0];
            const ulonglong2 b23 = *(const ulonglong2*)&sBd[l2][dj0 + 2];
            acc[0][0] = ffma2(av.x, b01.x, acc[0][0]);
            acc[1][0] = ffma2(av.y, b01.x, acc[1][0]);
            acc[0][1] = ffma2(av.x, b01.y, acc[0][1]);
            acc[1][1] = ffma2(av.y, b01.y, acc[1][1]);
            acc[0][2] = ffma2(av.x, b23.x, acc[0][2]);
            acc[1][2] = ffma2(av.y, b23.x, acc[1][2]);
            acc[0][3] = ffma2(av.x, b23.y, acc[0][3]);
            acc[1][3] = ffma2(av.y, b23.y, acc[1][3]);
        }
    }

    float c[4][4];
#pragma unroll
    for (int pp = 0; pp < 2; pp++)
#pragma unroll
        for (int j = 0; j < 4; j++) {
            const float2 v = unpack2(acc[pp][j]);
            c[2 * pp][j] = v.x;
            c[2 * pp + 1][j] = v.y;
        }

    const size_t base = (size_t)b * D2 * D2;
#pragma unroll
    for (int ii = 0; ii < 4; ii++)
        *(float4*)(g_A + base + (size_t)(ti * 64 + di0 + ii) * D2 + tj * 64 + dj0) =
            make_float4(c[ii][0], c[ii][1], c[ii][2], c[ii][3]);
    if (ti != tj) {
#pragma unroll
        for (int jj = 0; jj < 4; jj++)
            *(float4*)(g_A + base + (size_t)(tj * 64 + dj0 + jj) * D2 + ti * 64 + di0) =
                make_float4(c[0][jj], c[1][jj], c[2][jj], c[3][jj]);
    }
}

// ---------------------------------------------------------------------------
// Kernel 3: Xty
// ---------------------------------------------------------------------------
__global__ __launch_bounds__(256) void xty_kernel(const float* __restrict__ x)
{
    const int b    = blockIdx.x;
    const int dd   = threadIdx.x;
    const int half = dd >> 7;
    const int r    = dd & 127;

    float acc = 0.0f;
#pragma unroll 1
    for (int i = 0; i < 63; i++) {
        const float* tgt_row = x + (size_t)b * (H_DIM * W_DIM) + (i + 1) * W_DIM + 1;
#pragma unroll 4
        for (int j = 0; j < 63; j++) {
            const int cell = (half == 0) ? ((i + 1) * W_DIM + j) : (i * W_DIM + j + 1);
            const float v = g_S[((size_t)cell * B_DIM + b) * R_DIM + r];
            acc = fmaf(v, tgt_row[j], acc);
        }
    }
    g_y[(size_t)b * D2 + dd] = acc;
}

// ---------------------------------------------------------------------------
// Kernel 4: blocked Cholesky solve (NB=32).  Diagonal factor is warp-0
// register-resident + shuffle (no CTA barriers); panel solve + trailing
// update CTA-parallel; forward/backward triangular solves warp-synchronous
// in warp 0 (8 rows/lane, no barriers).
// ---------------------------------------------------------------------------
#define PK_ELEMS (D2 * (D2 + 1) / 2)                 // 32896
#define LP_STRIDE 36
#define LP_FLOATS (224 * LP_STRIDE)                  // 8064
#define SOLVE_SMEM ((PK_ELEMS + LP_FLOATS + D2) * 4)

__device__ __forceinline__ int pkrow(int i) { return (i * (i + 1)) >> 1; }

__device__ __forceinline__ int tri_row(int e)
{
    int a = (int)((sqrtf(8.0f * (float)e + 1.0f) - 1.0f) * 0.5f);
    while (pkrow(a) > e) a--;
    while (pkrow(a + 1) <= e) a++;
    return a;
}

__global__ __launch_bounds__(256) void solve_kernel(float* __restrict__ out)
{
    extern __shared__ float smref[];
    float* P   = smref;
    float* Lp  = smref + PK_ELEMS;
    float* riv = Lp + LP_FLOATS;

    const int b = blockIdx.x;
    const int t = threadIdx.x;
    const float* A = g_A + (size_t)b * D2 * D2;

    // load packed lower triangle + ridge
#pragma unroll 1
    for (int i = 0; i < D2; i++) {
        const int base = pkrow(i);
        for (int j = t; j <= i; j += 256)
            P[base + j] = A[(size_t)i * D2 + j] + ((j == i) ? 0.9f : 0.0f);
    }
    __syncthreads();

#pragma unroll 1
    for (int kb = 0; kb < 8; kb++) {
        const int base = kb * 32;

        // ---- warp 0: factor 32x32 diagonal block in registers ----
        if (t < 32) {
            const int lane = t;
            const int rowbase = pkrow(base + lane) + base;
            float v[32];
#pragma unroll
            for (int m = 0; m < 32; m++)
                v[m] = (m <= lane) ? P[rowbase + m] : 0.0f;
#pragma unroll
            for (int j = 0; j < 32; j++) {
                const float piv = __shfl_sync(0xffffffffu, v[j], j);
                const float ri = rsqrtf(piv) ;
                const float ri2 = 1.0f / sqrtf(piv);
                (void)ri;
                if (lane == j) riv[base + j] = ri2;
                if (lane > j) v[j] *= ri2;
#pragma unroll
                for (int m = j + 1; m < 32; m++) {
                    const float Lmj = __shfl_sync(0xffffffffu, v[j], m);
                    if (lane >= m) v[m] = fmaf(-v[j], Lmj, v[m]);
                }
            }
#pragma unroll
            for (int m = 0; m < 32; m++)
                if (m < lane) P[rowbase + m] = v[m];
        }
        __syncthreads();

        const int rows = D2 - base - 32;
        if (rows > 0) {
            // ---- panel triangular solve: one row per thread, no syncs ----
            if (t < rows) {
                const int gi = base + 32 + t;
                const int rb = pkrow(gi) + base;
                float v[32];
#pragma unroll
                for (int m = 0; m < 32; m++) v[m] = P[rb + m];
#pragma unroll
                for (int j = 0; j < 32; j++) {
                    float s = v[j];
                    const int lb = pkrow(base + j) + base;
#pragma unroll
                    for (int m = 0; m < 32; m++) {
                        if (m < j) s -= v[m] * P[lb + m];
                    }
                    v[j] = s * riv[base + j];
                }
#pragma unroll
                for (int m = 0; m < 32; m++) {
                    P[rb + m] = v[m];
                    Lp[t * LP_STRIDE + m] = v[m];
                }
            }
            __syncthreads();

            // ---- trailing update: A22 -= L21 L21^T ----
            const int cnt = (rows * (rows + 1)) >> 1;
            for (int e = t; e < cnt; e += 256) {
                const int a = tri_row(e);
                const int jloc = e - pkrow(a);
                const float4* ra = (const float4*)(Lp + a * LP_STRIDE);
                const float4* rj = (const float4*)(Lp + jloc * LP_STRIDE);
                float s = 0.0f;
#pragma unroll
                for (int mm = 0; mm < 8; mm++) {
                    const float4 u4 = ra[mm];
                    const float4 v4 = rj[mm];
                    s = fmaf(u4.x, v4.x, s);
                    s = fmaf(u4.y, v4.y, s);
                    s = fmaf(u4.z, v4.z, s);
                    s = fmaf(u4.w, v4.w, s);
                }
                const int gi = base + 32 + a;
                const int gj = base + 32 + jloc;
                P[pkrow(gi) + gj] -= s;
            }
            __syncthreads();
        }
    }

    // ---- warp 0: forward + backward triangular solves, 8 rows/lane ----
    if (t < 32) {
        const int lane = t;
        float z[8], rv[8];
        int rb[8];
#pragma unroll
        for (int s = 0; s < 8; s++) {
            const int i = s * 32 + lane;
            z[s]  = g_y[(size_t)b * D2 + i];
            rv[s] = riv[i];
            rb[s] = pkrow(i);
        }
        // forward: L zf = y
#pragma unroll 1
        for (int kk = 0; kk < 8; kk++) {
#pragma unroll
            for (int k2 = 0; k2 < 32; k2++) {
                const int k = kk * 32 + k2;
                const float xk = __shfl_sync(0xffffffffu, z[kk], k2)
                               * __shfl_sync(0xffffffffu, rv[kk], k2);
                if (lane == k2) z[kk] = xk;
#pragma unroll
                for (int s = 0; s < 8; s++) {
                    const int i = s * 32 + lane;
                    if (s >= kk && i > k)
                        z[s] = fmaf(-P[rb[s] + k], xk, z[s]);
                }
            }
        }
        // backward: L^T w = zf
#pragma unroll 1
        for (int kk = 7; kk >= 0; kk--) {
#pragma unroll
            for (int k2 = 31; k2 >= 0; k2--) {
                const int k = kk * 32 + k2;
                const float wk = __shfl_sync(0xffffffffu, z[kk], k2)
                               * __shfl_sync(0xffffffffu, rv[kk], k2);
                if (lane == k2) z[kk] = wk;
                const int pk = pkrow(k);
#pragma unroll
                for (int s = 0; s < 8; s++) {
                    const int i = s * 32 + lane;
                    if (s <= kk && i < k)
                        z[s] = fmaf(-P[pk + i], wk, z[s]);
                }
            }
        }
#pragma unroll
        for (int s = 0; s < 8; s++)
            out[(size_t)b * D2 + s * 32 + lane] = z[s];
    }
}

// ---------------------------------------------------------------------------
// kernel_launch
// ---------------------------------------------------------------------------
extern "C" void kernel_launch(void* const* d_in, const int* in_sizes, int n_in,
                              void* d_out, int out_size)
{
    const float* x   = (const float*)d_in[0];
    const float* Win = (const float*)d_in[1];
    const float* W1  = (const float*)d_in[2];
    const float* W2  = (const float*)d_in[3];
    float* out = (float*)d_out;
    (void)in_sizes; (void)n_in; (void)out_size;

    cudaFuncSetAttribute(esn_cluster,
                         cudaFuncAttributeMaxDynamicSharedMemorySize, ESN_SMEM);
    cudaFuncSetAttribute(solve_kernel,
                         cudaFuncAttributeMaxDynamicSharedMemorySize, SOLVE_SMEM);

    esn_cluster<<<2 * B_DIM, 1024, ESN_SMEM>>>(x, Win, W1, W2);
    xtx_kernel<<<dim3(10, B_DIM), 256>>>();
    xty_kernel<<<B_DIM, 256>>>(x);
    solve_kernel<<<B_DIM, 256, SOLVE_SMEM>>>(out);
}

// round 9
// speedup vs baseline: 1.0815x; 1.0815x over previous
#include <cuda_runtime.h>
#include <math.h>
#include <stdint.h>

typedef unsigned long long ull;

#define H_DIM 64
#define W_DIM 64
#define B_DIM 64
#define R_DIM 128
#define D2    256
#define LPOS  (63*63)

// scratch (device globals; no runtime allocation)
__device__ float g_S[(size_t)H_DIM * W_DIM * B_DIM * R_DIM];  // [cell][b][r]
__device__ float g_A[(size_t)B_DIM * D2 * D2];
__device__ float g_y[(size_t)B_DIM * D2];

// ---------------------------------------------------------------------------
// packed fp32x2 + cluster helpers
// ---------------------------------------------------------------------------
__device__ __forceinline__ ull ffma2(ull a, ull b, ull c)
{
    ull d;
    asm("fma.rn.f32x2 %0, %1, %2, %3;" : "=l"(d) : "l"(a), "l"(b), "l"(c));
    return d;
}
__device__ __forceinline__ ull fadd2(ull a, ull b)
{
    ull d;
    asm("add.rn.f32x2 %0, %1, %2;" : "=l"(d) : "l"(a), "l"(b));
    return d;
}
__device__ __forceinline__ float2 unpack2(ull v)
{
    float2 r;
    asm("mov.b64 {%0, %1}, %2;" : "=f"(r.x), "=f"(r.y) : "l"(v));
    return r;
}
__device__ __forceinline__ ull pack2(float a, float b)
{
    ull d;
    asm("mov.b64 %0, {%1, %2};" : "=l"(d) : "f"(a), "f"(b));
    return d;
}
__device__ __forceinline__ uint32_t smem_u32(const void* p)
{
    uint32_t a;
    asm("{ .reg .u64 t; cvta.to.shared.u64 t, %1; cvt.u32.u64 %0, t; }"
        : "=r"(a) : "l"(p));
    return a;
}
__device__ __forceinline__ void st_cluster_b32(uint32_t addr, float v)
{
    asm volatile("st.shared::cluster.b32 [%0], %1;" :: "r"(addr), "f"(v) : "memory");
}
#define CLUSTER_SYNC() do { \
    asm volatile("barrier.cluster.arrive.aligned;" ::: "memory"); \
    asm volatile("barrier.cluster.wait.aligned;"   ::: "memory"); \
} while (0)

// ---------------------------------------------------------------------------
// Kernel 1: ESN recurrence.  2-CTA cluster per batch; CTA rank owns the
// r-half [rank*64, rank*64+64).  Wavefront over anti-diagonals, chunks of 16
// cells between barrier pairs.  1024 threads:
//   g  = t >> 7       : 8 k-groups of 32 k (g<4 -> W1/left, g>=4 -> W2/above)
//   subcell = (t>>6)&1: which of 2 cells handled per pass (8 passes/chunk)
//   r  = t & 63       : output unit within my half
// K-PACKED f32x2.  Pass loop is unroll 1 to keep live registers under the
// 64-reg cap at 1024 threads (wreg[16]=32 regs must stay in the RF).
// ---------------------------------------------------------------------------
#define CCH 16
#define ESN_BUF_FLOATS (65 * 128)
#define ESN_BUF_BYTES  (ESN_BUF_FLOATS * 4)                  // 33280
#define ESN_SMEM (2 * ESN_BUF_BYTES + CCH * 8 * 64 * 8)      // 66560 + 65536

__global__ __launch_bounds__(1024, 1) __cluster_dims__(2, 1, 1)
void esn_cluster(const float* __restrict__ x, const float* __restrict__ Win,
                 const float* __restrict__ W1, const float* __restrict__ W2)
{
    extern __shared__ float sm[];
    float* buf0 = sm;                          // [65][128] diag states
    float* buf1 = sm + ESN_BUF_FLOATS;
    ull*   red  = (ull*)(sm + 2 * ESN_BUF_FLOATS);   // [16][8][64]

    uint32_t rank;
    asm("mov.u32 %0, %%cluster_ctarank;" : "=r"(rank));
    const int b  = blockIdx.x >> 1;
    const int t  = threadIdx.x;
    const int g  = t >> 7;                     // 0..7
    const int subcell = (t >> 6) & 1;
    const int r  = t & 63;

    const int rbase = (int)(rank << 6);
    const int rcol  = rbase + r;
    const int kloc  = (g & 3) << 5;            // 0,32,64,96 within the matrix

    // one-time: 16 k-pair weight columns into registers
    const float* Wsrc = (g < 4) ? W1 : W2;
    ull wreg[16];
#pragma unroll
    for (int j = 0; j < 16; j++) {
        const int k = kloc + 2 * j;
        wreg[j] = pack2(Wsrc[k * R_DIM + rcol], Wsrc[(k + 1) * R_DIM + rcol]);
    }
    const float winr = Win[rcol];
    const float* xb = x + ((size_t)b << 12);

    const uint32_t my_base = smem_u32(sm);
    uint32_t peer_base;
    asm("mapa.shared::cluster.u32 %0, %1, %2;"
        : "=r"(peer_base) : "r"(my_base), "r"(rank ^ 1u));

    // zero both diagonal buffers (zero slots double as boundary guards)
    {
        float4* z = (float4*)sm;
        for (int u = t; u < (2 * ESN_BUF_FLOATS) / 4; u += 1024)
            z[u] = make_float4(0.f, 0.f, 0.f, 0.f);
    }
    __syncthreads();
    CLUSTER_SYNC();   // peer zeroing done before our DSMEM stores can land

    for (int d = 0; d < H_DIM + W_DIM - 1; d++) {
        const int hmin = (d > 63) ? d - 63 : 0;
        const int hmax = (d < 63) ? d : 63;
        float* prev = (d & 1) ? buf0 : buf1;
        float* cur  = (d & 1) ? buf1 : buf0;
        const uint32_t cur_off = (d & 1) ? (uint32_t)ESN_BUF_BYTES : 0u;

        for (int c0 = hmin; c0 <= hmax; c0 += CCH) {
            const int nc = (hmax - c0 + 1 < CCH) ? (hmax - c0 + 1) : CCH;

            // ---- phase 1: k-packed partial dot products ----
#pragma unroll 1
            for (int pass = 0; pass < 8; pass++) {
                const int ci = (pass << 1) | subcell;
                if (ci >= nc) break;           // ci monotone in pass
                const int h = c0 + ci;
                // left slot(h)=h+1 ; above slot(h-1)=h ; unwritten slots = 0
                const int slot = (g < 4) ? (h + 1) : h;
                const ulonglong2* src =
                    (const ulonglong2*)(prev + slot * 128 + kloc);
                ull a0 = 0ull, a1 = 0ull;
#pragma unroll
                for (int i = 0; i < 8; i++) {
                    const ulonglong2 s = src[i];       // 2x (s_2k, s_2k+1)
                    a0 = ffma2(s.x, wreg[2 * i],     a0);
                    a1 = ffma2(s.y, wreg[2 * i + 1], a1);
                }
                red[((ci << 3) + g) * 64 + r] = fadd2(a0, a1);
            }
            __syncthreads();

            // ---- phase 2: one (cell, r) output per thread ----
            {
                const int ci = t >> 6;
                if (ci < nc) {
                    const int h = c0 + ci;
                    const int w = d - h;
                    const ull* rr = red + (ci << 9) + r;
                    ull s0 = rr[0],       s1 = rr[64];
                    ull s2 = rr[2 * 64],  s3 = rr[3 * 64];
                    s0 = fadd2(s0, rr[4 * 64]);
                    s1 = fadd2(s1, rr[5 * 64]);
                    s2 = fadd2(s2, rr[6 * 64]);
                    s3 = fadd2(s3, rr[7 * 64]);
                    const float2 v = unpack2(fadd2(fadd2(s0, s1), fadd2(s2, s3)));
                    const float xv = __ldg(xb + (h << 6) + w);
                    const float o = tanhf(fmaf(xv, winr, v.x + v.y));
                    const int idx = (h + 1) * 128 + rcol;
                    cur[idx] = o;
                    st_cluster_b32(peer_base + cur_off + (uint32_t)idx * 4u, o);
                    g_S[((size_t)(((h << 6) + w) << 6) + b) * R_DIM + rcol] = o;
                }
            }
            __syncthreads();
        }
        CLUSTER_SYNC();   // publish DSMEM half-states before next diagonal
    }
}

// ---------------------------------------------------------------------------
// Kernel 2: XtX, symmetric, f32x2.  grid = (10 tile-pairs, 64 batches).
// ---------------------------------------------------------------------------
__global__ __launch_bounds__(256) void xtx_kernel()
{
    const int b = blockIdx.y;
    const int p = blockIdx.x;
    const int ti = (p < 4) ? 0 : (p < 7) ? 1 : (p < 9) ? 2 : 3;
    const int tbase = (ti == 0) ? 0 : (ti == 1) ? 4 : (ti == 2) ? 7 : 9;
    const int tj = ti + (p - tbase);

    const int t = threadIdx.x;
    const int di0 = (t & 15) << 2;
    const int dj0 = (t >> 4) << 2;

    __shared__ float  sA [16][64];
    __shared__ float2 sBd[16][64];

    ull acc[2][4];
#pragma unroll
    for (int pp = 0; pp < 2; pp++)
#pragma unroll
        for (int j = 0; j < 4; j++) acc[pp][j] = 0ull;

    const int lr = t >> 4;
    const int qq = t & 15;

#pragma unroll 1
    for (int l0 = 0; l0 < LPOS; l0 += 16) {
        __syncthreads();
        const int l = l0 + lr;
        float4 va = make_float4(0.f, 0.f, 0.f, 0.f);
        float4 vb = make_float4(0.f, 0.f, 0.f, 0.f);
        if (l < LPOS) {
            const int i = l / 63;
            const int j = l - i * 63;
            {
                const int cell = (ti < 2) ? ((i + 1) * W_DIM + j) : (i * W_DIM + j + 1);
                const int off  = (ti & 1) << 6;
                va = *(const float4*)(g_S + (((size_t)cell << 6) + b) * R_DIM + off + (qq << 2));
            }
            {
                const int cell = (tj < 2) ? ((i + 1) * W_DIM + j) : (i * W_DIM + j + 1);
                const int off  = (tj & 1) << 6;
                vb = *(const float4*)(g_S + (((size_t)cell << 6) + b) * R_DIM + off + (qq << 2));
            }
        }
        *(float4*)&sA[lr][qq << 2] = va;
        sBd[lr][(qq << 2) + 0] = make_float2(vb.x, vb.x);
        sBd[lr][(qq << 2) + 1] = make_float2(vb.y, vb.y);
        sBd[lr][(qq << 2) + 2] = make_float2(vb.z, vb.z);
        sBd[lr][(qq << 2) + 3] = make_float2(vb.w, vb.w);
        __syncthreads();

#pragma unroll
        for (int l2 = 0; l2 < 16; l2++) {
            const ulonglong2 av  = *(const ulonglong2*)&sA[l2][di0];
            const ulonglong2 b01 = *(const ulonglong2*)&sBd[l2][dj0];
            const ulonglong2 b23 = *(const ulonglong2*)&sBd[l2][dj0 + 2];
            acc[0][0] = ffma2(av.x, b01.x, acc[0][0]);
            acc[1][0] = ffma2(av.y, b01.x, acc[1][0]);
            acc[0][1] = ffma2(av.x, b01.y, acc[0][1]);
            acc[1][1] = ffma2(av.y, b01.y, acc[1][1]);
            acc[0][2] = ffma2(av.x, b23.x, acc[0][2]);
            acc[1][2] = ffma2(av.y, b23.x, acc[1][2]);
            acc[0][3] = ffma2(av.x, b23.y, acc[0][3]);
            acc[1][3] = ffma2(av.y, b23.y, acc[1][3]);
        }
    }

    float c[4][4];
#pragma unroll
    for (int pp = 0; pp < 2; pp++)
#pragma unroll
        for (int j = 0; j < 4; j++) {
            const float2 v = unpack2(acc[pp][j]);
            c[2 * pp][j] = v.x;
            c[2 * pp + 1][j] = v.y;
        }

    const size_t base = (size_t)b * D2 * D2;
#pragma unroll
    for (int ii = 0; ii < 4; ii++)
        *(float4*)(g_A + base + (size_t)(ti * 64 + di0 + ii) * D2 + tj * 64 + dj0) =
            make_float4(c[ii][0], c[ii][1], c[ii][2], c[ii][3]);
    if (ti != tj) {
#pragma unroll
        for (int jj = 0; jj < 4; jj++)
            *(float4*)(g_A + base + (size_t)(tj * 64 + dj0 + jj) * D2 + ti * 64 + di0) =
                make_float4(c[0][jj], c[1][jj], c[2][jj], c[3][jj]);
    }
}

// ---------------------------------------------------------------------------
// Kernel 3: Xty
// ---------------------------------------------------------------------------
__global__ __launch_bounds__(256) void xty_kernel(const float* __restrict__ x)
{
    const int b    = blockIdx.x;
    const int dd   = threadIdx.x;
    const int half = dd >> 7;
    const int r    = dd & 127;

    float acc = 0.0f;
#pragma unroll 1
    for (int i = 0; i < 63; i++) {
        const float* tgt_row = x + (size_t)b * (H_DIM * W_DIM) + (i + 1) * W_DIM + 1;
#pragma unroll 4
        for (int j = 0; j < 63; j++) {
            const int cell = (half == 0) ? ((i + 1) * W_DIM + j) : (i * W_DIM + j + 1);
            const float v = g_S[((size_t)cell * B_DIM + b) * R_DIM + r];
            acc = fmaf(v, tgt_row[j], acc);
        }
    }
    g_y[(size_t)b * D2 + dd] = acc;
}

// ---------------------------------------------------------------------------
// Kernel 4: blocked Cholesky solve (NB=32) -- REVERTED to the R7 version
// (measured 327us; the warp-0 variant of R8 measured 528us).
// ---------------------------------------------------------------------------
#define PK_ELEMS (D2 * (D2 + 1) / 2)                 // 32896
#define LP_STRIDE 36
#define LP_FLOATS (224 * LP_STRIDE)                  // 8064
#define SOLVE_SMEM ((PK_ELEMS + LP_FLOATS + 4 * D2) * 4)

__device__ __forceinline__ int pkrow(int i) { return (i * (i + 1)) >> 1; }

__device__ __forceinline__ int tri_row(int e)
{
    int a = (int)((sqrtf(8.0f * (float)e + 1.0f) - 1.0f) * 0.5f);
    while (pkrow(a) > e) a--;
    while (pkrow(a + 1) <= e) a++;
    return a;
}

__global__ __launch_bounds__(256) void solve_kernel(float* __restrict__ out)
{
    extern __shared__ float smref[];
    float* P   = smref;
    float* Lp  = smref + PK_ELEMS;
    float* dgv = Lp + LP_FLOATS;
    float* riv = dgv + D2;
    float* zz  = riv + D2;
    float* xs  = zz + D2;

    const int b = blockIdx.x;
    const int t = threadIdx.x;
    const float* A = g_A + (size_t)b * D2 * D2;

    // load packed lower triangle + ridge
#pragma unroll 1
    for (int i = 0; i < D2; i++) {
        const int base = pkrow(i);
        for (int j = t; j <= i; j += 256)
            P[base + j] = A[(size_t)i * D2 + j] + ((j == i) ? 0.9f : 0.0f);
    }
    zz[t] = g_y[(size_t)b * D2 + t];
    __syncthreads();

#pragma unroll 1
    for (int kb = 0; kb < 8; kb++) {
        const int base = kb * 32;

        // ---- factor 32x32 diagonal block ----
#pragma unroll 1
        for (int j = 0; j < 32; j++) {
            const int jj = base + j;
            const float dj = sqrtf(P[pkrow(jj) + jj]);   // stable since last sync
            const float ri = 1.0f / dj;
            if (t == 0) { dgv[jj] = dj; riv[jj] = ri; }
            if (t > j && t < 32) P[pkrow(base + t) + jj] *= ri;
            __syncthreads();
            const int rem = 31 - j;
            const int cnt = (rem * (rem + 1)) >> 1;
            for (int e = t; e < cnt; e += 256) {
                const int a = tri_row(e);
                const int mloc = e - pkrow(a);
                const int i = base + j + 1 + a;
                const int m = base + j + 1 + mloc;
                P[pkrow(i) + m] -= P[pkrow(i) + jj] * P[pkrow(m) + jj];
            }
            __syncthreads();
        }

        const int rows = D2 - base - 32;
        if (rows > 0) {
            // ---- panel triangular solve: one row per thread, no syncs ----
            if (t < rows) {
                const int gi = base + 32 + t;
                const int rb = pkrow(gi) + base;
                float v[32];
#pragma unroll
                for (int m = 0; m < 32; m++) v[m] = P[rb + m];
#pragma unroll
                for (int j = 0; j < 32; j++) {
                    float s = v[j];
                    const int lb = pkrow(base + j) + base;
#pragma unroll
                    for (int m = 0; m < 32; m++) {
                        if (m < j) s -= v[m] * P[lb + m];
                    }
                    v[j] = s * riv[base + j];
                }
#pragma unroll
                for (int m = 0; m < 32; m++) {
                    P[rb + m] = v[m];
                    Lp[t * LP_STRIDE + m] = v[m];
                }
            }
            __syncthreads();

            // ---- trailing update: A22 -= L21 L21^T ----
            const int cnt = (rows * (rows + 1)) >> 1;
            for (int e = t; e < cnt; e += 256) {
                const int a = tri_row(e);
                const int jloc = e - pkrow(a);
                const float4* ra = (const float4*)(Lp + a * LP_STRIDE);
                const float4* rj = (const float4*)(Lp + jloc * LP_STRIDE);
                float s = 0.0f;
#pragma unroll
                for (int mm = 0; mm < 8; mm++) {
                    const float4 u4 = ra[mm];
                    const float4 v4 = rj[mm];
                    s = fmaf(u4.x, v4.x, s);
                    s = fmaf(u4.y, v4.y, s);
                    s = fmaf(u4.z, v4.z, s);
                    s = fmaf(u4.w, v4.w, s);
                }
                const int gi = base + 32 + a;
                const int gj = base + 32 + jloc;
                P[pkrow(gi) + gj] -= s;
            }
            __syncthreads();
        }
    }

    // forward solve L z = y
#pragma unroll 1
    for (int k = 0; k < D2; k++) {
        __syncthreads();
        const float xk = zz[k] * riv[k];
        if (t == k) xs[k] = xk;
        if (t > k)  zz[t] -= P[pkrow(t) + k] * xk;
    }
    __syncthreads();

    // backward solve L^T w = z
#pragma unroll 1
    for (int k = D2 - 1; k >= 0; k--) {
        __syncthreads();
        const float wk = xs[k] * riv[k];
        if (t == k) out[(size_t)b * D2 + k] = wk;
        if (t < k)  xs[t] -= P[pkrow(k) + t] * wk;
    }
}

// ---------------------------------------------------------------------------
// kernel_launch
// ---------------------------------------------------------------------------
extern "C" void kernel_launch(void* const* d_in, const int* in_sizes, int n_in,
                              void* d_out, int out_size)
{
    const float* x   = (const float*)d_in[0];
    const float* Win = (const float*)d_in[1];
    const float* W1  = (const float*)d_in[2];
    const float* W2  = (const float*)d_in[3];
    float* out = (float*)d_out;
    (void)in_sizes; (void)n_in; (void)out_size;

    cudaFuncSetAttribute(esn_cluster,
                         cudaFuncAttributeMaxDynamicSharedMemorySize, ESN_SMEM);
    cudaFuncSetAttribute(solve_kernel,
                         cudaFuncAttributeMaxDynamicSharedMemorySize, SOLVE_SMEM);

    esn_cluster<<<2 * B_DIM, 1024, ESN_SMEM>>>(x, Win, W1, W2);
    xtx_kernel<<<dim3(10, B_DIM), 256>>>();
    xty_kernel<<<B_DIM, 256>>>(x);
    solve_kernel<<<B_DIM, 256, SOLVE_SMEM>>>(out);
}

// round 10
// speedup vs baseline: 1.4838x; 1.3720x over previous
#include <cuda_runtime.h>
#include <math.h>
#include <stdint.h>

typedef unsigned long long ull;

#define H_DIM 64
#define W_DIM 64
#define B_DIM 64
#define R_DIM 128
#define D2    256
#define LPOS  (63*63)

// scratch (device globals; no runtime allocation)
__device__ float g_S[(size_t)H_DIM * W_DIM * B_DIM * R_DIM];  // [cell][b][r]
__device__ float g_A[(size_t)B_DIM * D2 * D2];
__device__ float g_y[(size_t)B_DIM * D2];

// ---------------------------------------------------------------------------
// packed fp32x2 + cluster helpers
// ---------------------------------------------------------------------------
__device__ __forceinline__ ull ffma2(ull a, ull b, ull c)
{
    ull d;
    asm("fma.rn.f32x2 %0, %1, %2, %3;" : "=l"(d) : "l"(a), "l"(b), "l"(c));
    return d;
}
__device__ __forceinline__ ull fadd2(ull a, ull b)
{
    ull d;
    asm("add.rn.f32x2 %0, %1, %2;" : "=l"(d) : "l"(a), "l"(b));
    return d;
}
__device__ __forceinline__ float2 unpack2(ull v)
{
    float2 r;
    asm("mov.b64 {%0, %1}, %2;" : "=f"(r.x), "=f"(r.y) : "l"(v));
    return r;
}
__device__ __forceinline__ ull pack2(float a, float b)
{
    ull d;
    asm("mov.b64 %0, {%1, %2};" : "=l"(d) : "f"(a), "f"(b));
    return d;
}
__device__ __forceinline__ uint32_t smem_u32(const void* p)
{
    uint32_t a;
    asm("{ .reg .u64 t; cvta.to.shared.u64 t, %1; cvt.u32.u64 %0, t; }"
        : "=r"(a) : "l"(p));
    return a;
}
__device__ __forceinline__ void st_cluster_b32(uint32_t addr, float v)
{
    asm volatile("st.shared::cluster.b32 [%0], %1;" :: "r"(addr), "f"(v) : "memory");
}
#define CLUSTER_SYNC() do { \
    asm volatile("barrier.cluster.arrive.aligned;" ::: "memory"); \
    asm volatile("barrier.cluster.wait.aligned;"   ::: "memory"); \
} while (0)

// fast tanh: (1-e)/(1+e), e = exp(-2|z|); abs err ~1e-6, well inside the
// 1e-3 budget (tanh' <= 1, contraction rho=0.9 damps recurrence error).
__device__ __forceinline__ float fast_tanhf(float z)
{
    const float a = fabsf(z);
    const float e = __expf(-2.0f * a);
    const float r = __fdividef(1.0f - e, 1.0f + e);
    return copysignf(r, z);
}

// ---------------------------------------------------------------------------
// Kernel 1: ESN recurrence.  2-CTA cluster per batch; CTA rank owns the
// r-half [rank*64, rank*64+64).  Wavefront over anti-diagonals, chunks of 32
// cells between barrier pairs (CCH=32 halves barrier count vs 16).
// 1024 threads:
//   g  = t >> 7       : 8 k-groups of 32 k (g<4 -> W1/left, g>=4 -> W2/above)
//   subcell = (t>>6)&1: which of 2 cells handled per pass (16 passes/chunk)
//   r  = t & 63       : output unit within my half
// K-PACKED f32x2.  Pass loop unroll 1 keeps live registers under the 64-reg
// cap at 1024 threads (wreg[16]=32 regs must stay in the RF).
// ---------------------------------------------------------------------------
#define CCH 32
#define ESN_BUF_FLOATS (65 * 128)
#define ESN_BUF_BYTES  (ESN_BUF_FLOATS * 4)                  // 33280
#define ESN_SMEM (2 * ESN_BUF_BYTES + CCH * 8 * 64 * 8)      // 66560 + 131072

__global__ __launch_bounds__(1024, 1) __cluster_dims__(2, 1, 1)
void esn_cluster(const float* __restrict__ x, const float* __restrict__ Win,
                 const float* __restrict__ W1, const float* __restrict__ W2)
{
    extern __shared__ float sm[];
    float* buf0 = sm;                          // [65][128] diag states
    float* buf1 = sm + ESN_BUF_FLOATS;
    ull*   red  = (ull*)(sm + 2 * ESN_BUF_FLOATS);   // [32][8][64]

    uint32_t rank;
    asm("mov.u32 %0, %%cluster_ctarank;" : "=r"(rank));
    const int b  = blockIdx.x >> 1;
    const int t  = threadIdx.x;
    const int g  = t >> 7;                     // 0..7
    const int subcell = (t >> 6) & 1;
    const int r  = t & 63;

    const int rbase = (int)(rank << 6);
    const int rcol  = rbase + r;
    const int kloc  = (g & 3) << 5;            // 0,32,64,96 within the matrix

    // one-time: 16 k-pair weight columns into registers
    const float* Wsrc = (g < 4) ? W1 : W2;
    ull wreg[16];
#pragma unroll
    for (int j = 0; j < 16; j++) {
        const int k = kloc + 2 * j;
        wreg[j] = pack2(Wsrc[k * R_DIM + rcol], Wsrc[(k + 1) * R_DIM + rcol]);
    }
    const float winr = Win[rcol];
    const float* xb = x + ((size_t)b << 12);

    const uint32_t my_base = smem_u32(sm);
    uint32_t peer_base;
    asm("mapa.shared::cluster.u32 %0, %1, %2;"
        : "=r"(peer_base) : "r"(my_base), "r"(rank ^ 1u));

    // zero both diagonal buffers (zero slots double as boundary guards)
    {
        float4* z = (float4*)sm;
        for (int u = t; u < (2 * ESN_BUF_FLOATS) / 4; u += 1024)
            z[u] = make_float4(0.f, 0.f, 0.f, 0.f);
    }
    __syncthreads();
    CLUSTER_SYNC();   // peer zeroing done before our DSMEM stores can land

    for (int d = 0; d < H_DIM + W_DIM - 1; d++) {
        const int hmin = (d > 63) ? d - 63 : 0;
        const int hmax = (d < 63) ? d : 63;
        float* prev = (d & 1) ? buf0 : buf1;
        float* cur  = (d & 1) ? buf1 : buf0;
        const uint32_t cur_off = (d & 1) ? (uint32_t)ESN_BUF_BYTES : 0u;

        for (int c0 = hmin; c0 <= hmax; c0 += CCH) {
            const int nc = (hmax - c0 + 1 < CCH) ? (hmax - c0 + 1) : CCH;

            // ---- phase 1: k-packed partial dot products ----
#pragma unroll 1
            for (int pass = 0; pass < 16; pass++) {
                const int ci = (pass << 1) | subcell;
                if (ci >= nc) break;           // ci monotone in pass
                const int h = c0 + ci;
                // left slot(h)=h+1 ; above slot(h-1)=h ; unwritten slots = 0
                const int slot = (g < 4) ? (h + 1) : h;
                const ulonglong2* src =
                    (const ulonglong2*)(prev + slot * 128 + kloc);
                ull a0 = 0ull, a1 = 0ull;
#pragma unroll
                for (int i = 0; i < 8; i++) {
                    const ulonglong2 s = src[i];       // 2x (s_2k, s_2k+1)
                    a0 = ffma2(s.x, wreg[2 * i],     a0);
                    a1 = ffma2(s.y, wreg[2 * i + 1], a1);
                }
                red[((ci << 3) + g) * 64 + r] = fadd2(a0, a1);
            }
            __syncthreads();

            // ---- phase 2: one (cell, r) output per thread, 2 reps ----
#pragma unroll 1
            for (int rep = 0; rep < 2; rep++) {
                const int ci = (t >> 6) + (rep << 4);
                if (ci < nc) {
                    const int h = c0 + ci;
                    const int w = d - h;
                    const ull* rr = red + (ci << 9) + r;
                    ull s0 = rr[0],       s1 = rr[64];
                    ull s2 = rr[2 * 64],  s3 = rr[3 * 64];
                    s0 = fadd2(s0, rr[4 * 64]);
                    s1 = fadd2(s1, rr[5 * 64]);
                    s2 = fadd2(s2, rr[6 * 64]);
                    s3 = fadd2(s3, rr[7 * 64]);
                    const float2 v = unpack2(fadd2(fadd2(s0, s1), fadd2(s2, s3)));
                    const float xv = __ldg(xb + (h << 6) + w);
                    const float o = fast_tanhf(fmaf(xv, winr, v.x + v.y));
                    const int idx = (h + 1) * 128 + rcol;
                    cur[idx] = o;
                    st_cluster_b32(peer_base + cur_off + (uint32_t)idx * 4u, o);
                    g_S[((size_t)(((h << 6) + w) << 6) + b) * R_DIM + rcol] = o;
                }
            }
            __syncthreads();
        }
        CLUSTER_SYNC();   // publish DSMEM half-states before next diagonal
    }
}

// ---------------------------------------------------------------------------
// Kernel 2: XtX, symmetric, f32x2, WITH FUSED Xty.
// grid = (11, 64): p=0..9 -> XtX tile-pairs, p=10 -> Xty for that batch
// (light CTA, hides inside the XtX wave; removes a separate launch).
// ---------------------------------------------------------------------------
__global__ __launch_bounds__(256) void xtx_kernel(const float* __restrict__ x)
{
    const int b = blockIdx.y;
    const int p = blockIdx.x;
    const int t = threadIdx.x;

    if (p == 10) {
        // ---- fused Xty ----
        const int half = t >> 7;
        const int r    = t & 127;
        float acc = 0.0f;
#pragma unroll 1
        for (int i = 0; i < 63; i++) {
            const float* tgt_row = x + ((size_t)b << 12) + (i + 1) * W_DIM + 1;
#pragma unroll 4
            for (int j = 0; j < 63; j++) {
                const int cell = (half == 0) ? ((i + 1) * W_DIM + j)
                                             : (i * W_DIM + j + 1);
                const float v = g_S[((size_t)cell * B_DIM + b) * R_DIM + r];
                acc = fmaf(v, tgt_row[j], acc);
            }
        }
        g_y[(size_t)b * D2 + t] = acc;
        return;
    }

    const int ti = (p < 4) ? 0 : (p < 7) ? 1 : (p < 9) ? 2 : 3;
    const int tbase = (ti == 0) ? 0 : (ti == 1) ? 4 : (ti == 2) ? 7 : 9;
    const int tj = ti + (p - tbase);

    const int di0 = (t & 15) << 2;
    const int dj0 = (t >> 4) << 2;

    __shared__ float  sA [16][64];
    __shared__ float2 sBd[16][64];

    ull acc[2][4];
#pragma unroll
    for (int pp = 0; pp < 2; pp++)
#pragma unroll
        for (int j = 0; j < 4; j++) acc[pp][j] = 0ull;

    const int lr = t >> 4;
    const int qq = t & 15;

#pragma unroll 1
    for (int l0 = 0; l0 < LPOS; l0 += 16) {
        __syncthreads();
        const int l = l0 + lr;
        float4 va = make_float4(0.f, 0.f, 0.f, 0.f);
        float4 vb = make_float4(0.f, 0.f, 0.f, 0.f);
        if (l < LPOS) {
            const int i = l / 63;
            const int j = l - i * 63;
            {
                const int cell = (ti < 2) ? ((i + 1) * W_DIM + j) : (i * W_DIM + j + 1);
                const int off  = (ti & 1) << 6;
                va = *(const float4*)(g_S + (((size_t)cell << 6) + b) * R_DIM + off + (qq << 2));
            }
            {
                const int cell = (tj < 2) ? ((i + 1) * W_DIM + j) : (i * W_DIM + j + 1);
                const int off  = (tj & 1) << 6;
                vb = *(const float4*)(g_S + (((size_t)cell << 6) + b) * R_DIM + off + (qq << 2));
            }
        }
        *(float4*)&sA[lr][qq << 2] = va;
        sBd[lr][(qq << 2) + 0] = make_float2(vb.x, vb.x);
        sBd[lr][(qq << 2) + 1] = make_float2(vb.y, vb.y);
        sBd[lr][(qq << 2) + 2] = make_float2(vb.z, vb.z);
        sBd[lr][(qq << 2) + 3] = make_float2(vb.w, vb.w);
        __syncthreads();

#pragma unroll
        for (int l2 = 0; l2 < 16; l2++) {
            const ulonglong2 av  = *(const ulonglong2*)&sA[l2][di0];
            const ulonglong2 b01 = *(const ulonglong2*)&sBd[l2][dj0];
            const ulonglong2 b23 = *(const ulonglong2*)&sBd[l2][dj0 + 2];
            acc[0][0] = ffma2(av.x, b01.x, acc[0][0]);
            acc[1][0] = ffma2(av.y, b01.x, acc[1][0]);
            acc[0][1] = ffma2(av.x, b01.y, acc[0][1]);
            acc[1][1] = ffma2(av.y, b01.y, acc[1][1]);
            acc[0][2] = ffma2(av.x, b23.x, acc[0][2]);
            acc[1][2] = ffma2(av.y, b23.x, acc[1][2]);
            acc[0][3] = ffma2(av.x, b23.y, acc[0][3]);
            acc[1][3] = ffma2(av.y, b23.y, acc[1][3]);
        }
    }

    float c[4][4];
#pragma unroll
    for (int pp = 0; pp < 2; pp++)
#pragma unroll
        for (int j = 0; j < 4; j++) {
            const float2 v = unpack2(acc[pp][j]);
            c[2 * pp][j] = v.x;
            c[2 * pp + 1][j] = v.y;
        }

    const size_t base = (size_t)b * D2 * D2;
#pragma unroll
    for (int ii = 0; ii < 4; ii++)
        *(float4*)(g_A + base + (size_t)(ti * 64 + di0 + ii) * D2 + tj * 64 + dj0) =
            make_float4(c[ii][0], c[ii][1], c[ii][2], c[ii][3]);
    if (ti != tj) {
#pragma unroll
        for (int jj = 0; jj < 4; jj++)
            *(float4*)(g_A + base + (size_t)(tj * 64 + dj0 + jj) * D2 + ti * 64 + di0) =
                make_float4(c[0][jj], c[1][jj], c[2][jj], c[3][jj]);
    }
}

// ---------------------------------------------------------------------------
// Kernel 3: blocked Cholesky solve (NB=32), proven R7 version (327us).
// ---------------------------------------------------------------------------
#define PK_ELEMS (D2 * (D2 + 1) / 2)                 // 32896
#define LP_STRIDE 36
#define LP_FLOATS (224 * LP_STRIDE)                  // 8064
#define SOLVE_SMEM ((PK_ELEMS + LP_FLOATS + 4 * D2) * 4)

__device__ __forceinline__ int pkrow(int i) { return (i * (i + 1)) >> 1; }

__device__ __forceinline__ int tri_row(int e)
{
    int a = (int)((sqrtf(8.0f * (float)e + 1.0f) - 1.0f) * 0.5f);
    while (pkrow(a) > e) a--;
    while (pkrow(a + 1) <= e) a++;
    return a;
}

__global__ __launch_bounds__(256) void solve_kernel(float* __restrict__ out)
{
    extern __shared__ float smref[];
    float* P   = smref;
    float* Lp  = smref + PK_ELEMS;
    float* dgv = Lp + LP_FLOATS;
    float* riv = dgv + D2;
    float* zz  = riv + D2;
    float* xs  = zz + D2;

    const int b = blockIdx.x;
    const int t = threadIdx.x;
    const float* A = g_A + (size_t)b * D2 * D2;

    // load packed lower triangle + ridge
#pragma unroll 1
    for (int i = 0; i < D2; i++) {
        const int base = pkrow(i);
        for (int j = t; j <= i; j += 256)
            P[base + j] = A[(size_t)i * D2 + j] + ((j == i) ? 0.9f : 0.0f);
    }
    zz[t] = g_y[(size_t)b * D2 + t];
    __syncthreads();

#pragma unroll 1
    for (int kb = 0; kb < 8; kb++) {
        const int base = kb * 32;

        // ---- factor 32x32 diagonal block ----
#pragma unroll 1
        for (int j = 0; j < 32; j++) {
            const int jj = base + j;
            const float dj = sqrtf(P[pkrow(jj) + jj]);   // stable since last sync
            const float ri = 1.0f / dj;
            if (t == 0) { dgv[jj] = dj; riv[jj] = ri; }
            if (t > j && t < 32) P[pkrow(base + t) + jj] *= ri;
            __syncthreads();
            const int rem = 31 - j;
            const int cnt = (rem * (rem + 1)) >> 1;
            for (int e = t; e < cnt; e += 256) {
                const int a = tri_row(e);
                const int mloc = e - pkrow(a);
                const int i = base + j + 1 + a;
                const int m = base + j + 1 + mloc;
                P[pkrow(i) + m] -= P[pkrow(i) + jj] * P[pkrow(m) + jj];
            }
            __syncthreads();
        }

        const int rows = D2 - base - 32;
        if (rows > 0) {
            // ---- panel triangular solve: one row per thread, no syncs ----
            if (t < rows) {
                const int gi = base + 32 + t;
                const int rb = pkrow(gi) + base;
                float v[32];
#pragma unroll
                for (int m = 0; m < 32; m++) v[m] = P[rb + m];
#pragma unroll
                for (int j = 0; j < 32; j++) {
                    float s = v[j];
                    const int lb = pkrow(base + j) + base;
#pragma unroll
                    for (int m = 0; m < 32; m++) {
                        if (m < j) s -= v[m] * P[lb + m];
                    }
                    v[j] = s * riv[base + j];
                }
#pragma unroll
                for (int m = 0; m < 32; m++) {
                    P[rb + m] = v[m];
                    Lp[t * LP_STRIDE + m] = v[m];
                }
            }
            __syncthreads();

            // ---- trailing update: A22 -= L21 L21^T ----
            const int cnt = (rows * (rows + 1)) >> 1;
            for (int e = t; e < cnt; e += 256) {
                const int a = tri_row(e);
                const int jloc = e - pkrow(a);
                const float4* ra = (const float4*)(Lp + a * LP_STRIDE);
                const float4* rj = (const float4*)(Lp + jloc * LP_STRIDE);
                float s = 0.0f;
#pragma unroll
                for (int mm = 0; mm < 8; mm++) {
                    const float4 u4 = ra[mm];
                    const float4 v4 = rj[mm];
                    s = fmaf(u4.x, v4.x, s);
                    s = fmaf(u4.y, v4.y, s);
                    s = fmaf(u4.z, v4.z, s);
                    s = fmaf(u4.w, v4.w, s);
                }
                const int gi = base + 32 + a;
                const int gj = base + 32 + jloc;
                P[pkrow(gi) + gj] -= s;
            }
            __syncthreads();
        }
    }

    // forward solve L z = y
#pragma unroll 1
    for (int k = 0; k < D2; k++) {
        __syncthreads();
        const float xk = zz[k] * riv[k];
        if (t == k) xs[k] = xk;
        if (t > k)  zz[t] -= P[pkrow(t) + k] * xk;
    }
    __syncthreads();

    // backward solve L^T w = z
#pragma unroll 1
    for (int k = D2 - 1; k >= 0; k--) {
        __syncthreads();
        const float wk = xs[k] * riv[k];
        if (t == k) out[(size_t)b * D2 + k] = wk;
        if (t < k)  xs[t] -= P[pkrow(k) + t] * wk;
    }
}

// ---------------------------------------------------------------------------
// kernel_launch
// ---------------------------------------------------------------------------
extern "C" void kernel_launch(void* const* d_in, const int* in_sizes, int n_in,
                              void* d_out, int out_size)
{
    const float* x   = (const float*)d_in[0];
    const float* Win = (const float*)d_in[1];
    const float* W1  = (const float*)d_in[2];
    const float* W2  = (const float*)d_in[3];
    float* out = (float*)d_out;
    (void)in_sizes; (void)n_in; (void)out_size;

    cudaFuncSetAttribute(esn_cluster,
                         cudaFuncAttributeMaxDynamicSharedMemorySize, ESN_SMEM);
    cudaFuncSetAttribute(solve_kernel,
                         cudaFuncAttributeMaxDynamicSharedMemorySize, SOLVE_SMEM);

    esn_cluster<<<2 * B_DIM, 1024, ESN_SMEM>>>(x, Win, W1, W2);
    xtx_kernel<<<dim3(11, B_DIM), 256>>>(x);
    solve_kernel<<<B_DIM, 256, SOLVE_SMEM>>>(out);
}

// round 11
// speedup vs baseline: 1.6499x; 1.1119x over previous
#include <cuda_runtime.h>
#include <math.h>
#include <stdint.h>

typedef unsigned long long ull;

#define H_DIM 64
#define W_DIM 64
#define B_DIM 64
#define R_DIM 128
#define D2    256
#define LPOS  (63*63)

// scratch (device globals; no runtime allocation)
__device__ float g_S[(size_t)H_DIM * W_DIM * B_DIM * R_DIM];  // [cell][b][r]
__device__ float g_A[(size_t)B_DIM * D2 * D2];
__device__ float g_y[(size_t)B_DIM * D2];

// ---------------------------------------------------------------------------
// packed fp32x2 + cluster helpers
// ---------------------------------------------------------------------------
__device__ __forceinline__ ull ffma2(ull a, ull b, ull c)
{
    ull d;
    asm("fma.rn.f32x2 %0, %1, %2, %3;" : "=l"(d) : "l"(a), "l"(b), "l"(c));
    return d;
}
__device__ __forceinline__ ull fadd2(ull a, ull b)
{
    ull d;
    asm("add.rn.f32x2 %0, %1, %2;" : "=l"(d) : "l"(a), "l"(b));
    return d;
}
__device__ __forceinline__ float2 unpack2(ull v)
{
    float2 r;
    asm("mov.b64 {%0, %1}, %2;" : "=f"(r.x), "=f"(r.y) : "l"(v));
    return r;
}
__device__ __forceinline__ ull pack2(float a, float b)
{
    ull d;
    asm("mov.b64 %0, {%1, %2};" : "=l"(d) : "f"(a), "f"(b));
    return d;
}
__device__ __forceinline__ uint32_t smem_u32(const void* p)
{
    uint32_t a;
    asm("{ .reg .u64 t; cvta.to.shared.u64 t, %1; cvt.u32.u64 %0, t; }"
        : "=r"(a) : "l"(p));
    return a;
}
__device__ __forceinline__ void st_cluster_b32(uint32_t addr, float v)
{
    asm volatile("st.shared::cluster.b32 [%0], %1;" :: "r"(addr), "f"(v) : "memory");
}
#define CLUSTER_SYNC() do { \
    asm volatile("barrier.cluster.arrive.aligned;" ::: "memory"); \
    asm volatile("barrier.cluster.wait.aligned;"   ::: "memory"); \
} while (0)

// fast tanh: (1-e)/(1+e), e = exp(-2|z|); abs err ~1e-6, well inside budget.
__device__ __forceinline__ float fast_tanhf(float z)
{
    const float a = fabsf(z);
    const float e = __expf(-2.0f * a);
    const float r = __fdividef(1.0f - e, 1.0f + e);
    return copysignf(r, z);
}

// ---------------------------------------------------------------------------
// Kernel 1: ESN recurrence (unchanged from R10 -- measured at its f32x2
// issue floor: 875us, fma=33% == rt-3 issue-slot occupancy).
// ---------------------------------------------------------------------------
#define CCH 32
#define ESN_BUF_FLOATS (65 * 128)
#define ESN_BUF_BYTES  (ESN_BUF_FLOATS * 4)                  // 33280
#define ESN_SMEM (2 * ESN_BUF_BYTES + CCH * 8 * 64 * 8)      // 66560 + 131072

__global__ __launch_bounds__(1024, 1) __cluster_dims__(2, 1, 1)
void esn_cluster(const float* __restrict__ x, const float* __restrict__ Win,
                 const float* __restrict__ W1, const float* __restrict__ W2)
{
    extern __shared__ float sm[];
    float* buf0 = sm;                          // [65][128] diag states
    float* buf1 = sm + ESN_BUF_FLOATS;
    ull*   red  = (ull*)(sm + 2 * ESN_BUF_FLOATS);   // [32][8][64]

    uint32_t rank;
    asm("mov.u32 %0, %%cluster_ctarank;" : "=r"(rank));
    const int b  = blockIdx.x >> 1;
    const int t  = threadIdx.x;
    const int g  = t >> 7;                     // 0..7
    const int subcell = (t >> 6) & 1;
    const int r  = t & 63;

    const int rbase = (int)(rank << 6);
    const int rcol  = rbase + r;
    const int kloc  = (g & 3) << 5;            // 0,32,64,96 within the matrix

    // one-time: 16 k-pair weight columns into registers
    const float* Wsrc = (g < 4) ? W1 : W2;
    ull wreg[16];
#pragma unroll
    for (int j = 0; j < 16; j++) {
        const int k = kloc + 2 * j;
        wreg[j] = pack2(Wsrc[k * R_DIM + rcol], Wsrc[(k + 1) * R_DIM + rcol]);
    }
    const float winr = Win[rcol];
    const float* xb = x + ((size_t)b << 12);

    const uint32_t my_base = smem_u32(sm);
    uint32_t peer_base;
    asm("mapa.shared::cluster.u32 %0, %1, %2;"
        : "=r"(peer_base) : "r"(my_base), "r"(rank ^ 1u));

    // zero both diagonal buffers (zero slots double as boundary guards)
    {
        float4* z = (float4*)sm;
        for (int u = t; u < (2 * ESN_BUF_FLOATS) / 4; u += 1024)
            z[u] = make_float4(0.f, 0.f, 0.f, 0.f);
    }
    // block 0 of each cluster pair also zeroes g_y slices (consumed by the
    // fused xty atomics-free path; harmless redundancy avoided: rank 0 only)
    __syncthreads();
    CLUSTER_SYNC();   // peer zeroing done before our DSMEM stores can land

    for (int d = 0; d < H_DIM + W_DIM - 1; d++) {
        const int hmin = (d > 63) ? d - 63 : 0;
        const int hmax = (d < 63) ? d : 63;
        float* prev = (d & 1) ? buf0 : buf1;
        float* cur  = (d & 1) ? buf1 : buf0;
        const uint32_t cur_off = (d & 1) ? (uint32_t)ESN_BUF_BYTES : 0u;

        for (int c0 = hmin; c0 <= hmax; c0 += CCH) {
            const int nc = (hmax - c0 + 1 < CCH) ? (hmax - c0 + 1) : CCH;

            // ---- phase 1: k-packed partial dot products ----
#pragma unroll 1
            for (int pass = 0; pass < 16; pass++) {
                const int ci = (pass << 1) | subcell;
                if (ci >= nc) break;           // ci monotone in pass
                const int h = c0 + ci;
                const int slot = (g < 4) ? (h + 1) : h;
                const ulonglong2* src =
                    (const ulonglong2*)(prev + slot * 128 + kloc);
                ull a0 = 0ull, a1 = 0ull;
#pragma unroll
                for (int i = 0; i < 8; i++) {
                    const ulonglong2 s = src[i];       // 2x (s_2k, s_2k+1)
                    a0 = ffma2(s.x, wreg[2 * i],     a0);
                    a1 = ffma2(s.y, wreg[2 * i + 1], a1);
                }
                red[((ci << 3) + g) * 64 + r] = fadd2(a0, a1);
            }
            __syncthreads();

            // ---- phase 2: one (cell, r) output per thread, 2 reps ----
#pragma unroll 1
            for (int rep = 0; rep < 2; rep++) {
                const int ci = (t >> 6) + (rep << 4);
                if (ci < nc) {
                    const int h = c0 + ci;
                    const int w = d - h;
                    const ull* rr = red + (ci << 9) + r;
                    ull s0 = rr[0],       s1 = rr[64];
                    ull s2 = rr[2 * 64],  s3 = rr[3 * 64];
                    s0 = fadd2(s0, rr[4 * 64]);
                    s1 = fadd2(s1, rr[5 * 64]);
                    s2 = fadd2(s2, rr[6 * 64]);
                    s3 = fadd2(s3, rr[7 * 64]);
                    const float2 v = unpack2(fadd2(fadd2(s0, s1), fadd2(s2, s3)));
                    const float xv = __ldg(xb + (h << 6) + w);
                    const float o = fast_tanhf(fmaf(xv, winr, v.x + v.y));
                    const int idx = (h + 1) * 128 + rcol;
                    cur[idx] = o;
                    st_cluster_b32(peer_base + cur_off + (uint32_t)idx * 4u, o);
                    g_S[((size_t)(((h << 6) + w) << 6) + b) * R_DIM + rcol] = o;
                }
            }
            __syncthreads();
        }
        CLUSTER_SYNC();   // publish DSMEM half-states before next diagonal
    }
}

// ---------------------------------------------------------------------------
// Kernel 2: XtX, symmetric, f32x2, WITH FUSED Xty.  B duplication moved from
// smem into registers (sB stored plain; packed (b,b) operands built with ALU
// movs): LDS per l2-step 3 -> 2, crossbar traffic -33%.
// grid = (11, 64): p=0..9 -> XtX tile-pairs, p=10 -> Xty for that batch.
// ---------------------------------------------------------------------------
__global__ __launch_bounds__(256) void xtx_kernel(const float* __restrict__ x)
{
    const int b = blockIdx.y;
    const int p = blockIdx.x;
    const int t = threadIdx.x;

    if (p == 10) {
        // ---- fused Xty ----
        const int half = t >> 7;
        const int r    = t & 127;
        float acc = 0.0f;
#pragma unroll 1
        for (int i = 0; i < 63; i++) {
            const float* tgt_row = x + ((size_t)b << 12) + (i + 1) * W_DIM + 1;
#pragma unroll 4
            for (int j = 0; j < 63; j++) {
                const int cell = (half == 0) ? ((i + 1) * W_DIM + j)
                                             : (i * W_DIM + j + 1);
                const float v = g_S[((size_t)cell * B_DIM + b) * R_DIM + r];
                acc = fmaf(v, tgt_row[j], acc);
            }
        }
        g_y[(size_t)b * D2 + t] = acc;
        return;
    }

    const int ti = (p < 4) ? 0 : (p < 7) ? 1 : (p < 9) ? 2 : 3;
    const int tbase = (ti == 0) ? 0 : (ti == 1) ? 4 : (ti == 2) ? 7 : 9;
    const int tj = ti + (p - tbase);

    const int di0 = (t & 15) << 2;
    const int dj0 = (t >> 4) << 2;

    __shared__ float sA[16][64];
    __shared__ float sB[16][64];

    ull acc[2][4];
#pragma unroll
    for (int pp = 0; pp < 2; pp++)
#pragma unroll
        for (int j = 0; j < 4; j++) acc[pp][j] = 0ull;

    const int lr = t >> 4;
    const int qq = t & 15;

#pragma unroll 1
    for (int l0 = 0; l0 < LPOS; l0 += 16) {
        __syncthreads();
        const int l = l0 + lr;
        float4 va = make_float4(0.f, 0.f, 0.f, 0.f);
        float4 vb = make_float4(0.f, 0.f, 0.f, 0.f);
        if (l < LPOS) {
            const int i = l / 63;
            const int j = l - i * 63;
            {
                const int cell = (ti < 2) ? ((i + 1) * W_DIM + j) : (i * W_DIM + j + 1);
                const int off  = (ti & 1) << 6;
                va = *(const float4*)(g_S + (((size_t)cell << 6) + b) * R_DIM + off + (qq << 2));
            }
            {
                const int cell = (tj < 2) ? ((i + 1) * W_DIM + j) : (i * W_DIM + j + 1);
                const int off  = (tj & 1) << 6;
                vb = *(const float4*)(g_S + (((size_t)cell << 6) + b) * R_DIM + off + (qq << 2));
            }
        }
        *(float4*)&sA[lr][qq << 2] = va;
        *(float4*)&sB[lr][qq << 2] = vb;
        __syncthreads();

#pragma unroll
        for (int l2 = 0; l2 < 16; l2++) {
            const ulonglong2 av = *(const ulonglong2*)&sA[l2][di0];
            const float4 bv = *(const float4*)&sB[l2][dj0];
            const ull b0 = pack2(bv.x, bv.x);
            const ull b1 = pack2(bv.y, bv.y);
            const ull b2 = pack2(bv.z, bv.z);
            const ull b3 = pack2(bv.w, bv.w);
            acc[0][0] = ffma2(av.x, b0, acc[0][0]);
            acc[1][0] = ffma2(av.y, b0, acc[1][0]);
            acc[0][1] = ffma2(av.x, b1, acc[0][1]);
            acc[1][1] = ffma2(av.y, b1, acc[1][1]);
            acc[0][2] = ffma2(av.x, b2, acc[0][2]);
            acc[1][2] = ffma2(av.y, b2, acc[1][2]);
            acc[0][3] = ffma2(av.x, b3, acc[0][3]);
            acc[1][3] = ffma2(av.y, b3, acc[1][3]);
        }
    }

    float c[4][4];
#pragma unroll
    for (int pp = 0; pp < 2; pp++)
#pragma unroll
        for (int j = 0; j < 4; j++) {
            const float2 v = unpack2(acc[pp][j]);
            c[2 * pp][j] = v.x;
            c[2 * pp + 1][j] = v.y;
        }

    const size_t base = (size_t)b * D2 * D2;
#pragma unroll
    for (int ii = 0; ii < 4; ii++)
        *(float4*)(g_A + base + (size_t)(ti * 64 + di0 + ii) * D2 + tj * 64 + dj0) =
            make_float4(c[ii][0], c[ii][1], c[ii][2], c[ii][3]);
    if (ti != tj) {
#pragma unroll
        for (int jj = 0; jj < 4; jj++)
            *(float4*)(g_A + base + (size_t)(tj * 64 + dj0 + jj) * D2 + ti * 64 + di0) =
                make_float4(c[0][jj], c[1][jj], c[2][jj], c[3][jj]);
    }
}

// ---------------------------------------------------------------------------
// Kernel 3: blocked Cholesky solve (NB=32), R7 structure, now 512 threads:
// halves the elementwise phases (load, rank-1 updates, trailing update);
// barrier-bound phases unchanged.  Guards added for t>=256.
// ---------------------------------------------------------------------------
#define SOLVE_T 512
#define PK_ELEMS (D2 * (D2 + 1) / 2)                 // 32896
#define LP_STRIDE 36
#define LP_FLOATS (224 * LP_STRIDE)                  // 8064
#define SOLVE_SMEM ((PK_ELEMS + LP_FLOATS + 4 * D2) * 4)

__device__ __forceinline__ int pkrow(int i) { return (i * (i + 1)) >> 1; }

__device__ __forceinline__ int tri_row(int e)
{
    int a = (int)((sqrtf(8.0f * (float)e + 1.0f) - 1.0f) * 0.5f);
    while (pkrow(a) > e) a--;
    while (pkrow(a + 1) <= e) a++;
    return a;
}

__global__ __launch_bounds__(SOLVE_T) void solve_kernel(float* __restrict__ out)
{
    extern __shared__ float smref[];
    float* P   = smref;
    float* Lp  = smref + PK_ELEMS;
    float* dgv = Lp + LP_FLOATS;
    float* riv = dgv + D2;
    float* zz  = riv + D2;
    float* xs  = zz + D2;

    const int b = blockIdx.x;
    const int t = threadIdx.x;
    const float* A = g_A + (size_t)b * D2 * D2;

    // load packed lower triangle + ridge
#pragma unroll 1
    for (int i = 0; i < D2; i++) {
        const int base = pkrow(i);
        for (int j = t; j <= i; j += SOLVE_T)
            P[base + j] = A[(size_t)i * D2 + j] + ((j == i) ? 0.9f : 0.0f);
    }
    if (t < D2) zz[t] = g_y[(size_t)b * D2 + t];
    __syncthreads();

#pragma unroll 1
    for (int kb = 0; kb < 8; kb++) {
        const int base = kb * 32;

        // ---- factor 32x32 diagonal block ----
#pragma unroll 1
        for (int j = 0; j < 32; j++) {
            const int jj = base + j;
            const float dj = sqrtf(P[pkrow(jj) + jj]);   // stable since last sync
            const float ri = 1.0f / dj;
            if (t == 0) { dgv[jj] = dj; riv[jj] = ri; }
            if (t > j && t < 32) P[pkrow(base + t) + jj] *= ri;
            __syncthreads();
            const int rem = 31 - j;
            const int cnt = (rem * (rem + 1)) >> 1;
            for (int e = t; e < cnt; e += SOLVE_T) {
                const int a = tri_row(e);
                const int mloc = e - pkrow(a);
                const int i = base + j + 1 + a;
                const int m = base + j + 1 + mloc;
                P[pkrow(i) + m] -= P[pkrow(i) + jj] * P[pkrow(m) + jj];
            }
            __syncthreads();
        }

        const int rows = D2 - base - 32;
        if (rows > 0) {
            // ---- panel triangular solve: one row per thread, no syncs ----
            if (t < rows) {
                const int gi = base + 32 + t;
                const int rb = pkrow(gi) + base;
                float v[32];
#pragma unroll
                for (int m = 0; m < 32; m++) v[m] = P[rb + m];
#pragma unroll
                for (int j = 0; j < 32; j++) {
                    float s = v[j];
                    const int lb = pkrow(base + j) + base;
#pragma unroll
                    for (int m = 0; m < 32; m++) {
                        if (m < j) s -= v[m] * P[lb + m];
                    }
                    v[j] = s * riv[base + j];
                }
#pragma unroll
                for (int m = 0; m < 32; m++) {
                    P[rb + m] = v[m];
                    Lp[t * LP_STRIDE + m] = v[m];
                }
            }
            __syncthreads();

            // ---- trailing update: A22 -= L21 L21^T ----
            const int cnt = (rows * (rows + 1)) >> 1;
            for (int e = t; e < cnt; e += SOLVE_T) {
                const int a = tri_row(e);
                const int jloc = e - pkrow(a);
                const float4* ra = (const float4*)(Lp + a * LP_STRIDE);
                const float4* rj = (const float4*)(Lp + jloc * LP_STRIDE);
                float s = 0.0f;
#pragma unroll
                for (int mm = 0; mm < 8; mm++) {
                    const float4 u4 = ra[mm];
                    const float4 v4 = rj[mm];
                    s = fmaf(u4.x, v4.x, s);
                    s = fmaf(u4.y, v4.y, s);
                    s = fmaf(u4.z, v4.z, s);
                    s = fmaf(u4.w, v4.w, s);
                }
                const int gi = base + 32 + a;
                const int gj = base + 32 + jloc;
                P[pkrow(gi) + gj] -= s;
            }
            __syncthreads();
        }
    }

    // forward solve L z = y
#pragma unroll 1
    for (int k = 0; k < D2; k++) {
        __syncthreads();
        const float xk = zz[k] * riv[k];
        if (t == k) xs[k] = xk;
        if (t > k && t < D2) zz[t] -= P[pkrow(t) + k] * xk;
    }
    __syncthreads();

    // backward solve L^T w = z
#pragma unroll 1
    for (int k = D2 - 1; k >= 0; k--) {
        __syncthreads();
        const float wk = xs[k] * riv[k];
        if (t == k) out[(size_t)b * D2 + k] = wk;
        if (t < k)  xs[t] -= P[pkrow(k) + t] * wk;
    }
}

// ---------------------------------------------------------------------------
// kernel_launch
// ---------------------------------------------------------------------------
extern "C" void kernel_launch(void* const* d_in, const int* in_sizes, int n_in,
                              void* d_out, int out_size)
{
    const float* x   = (const float*)d_in[0];
    const float* Win = (const float*)d_in[1];
    const float* W1  = (const float*)d_in[2];
    const float* W2  = (const float*)d_in[3];
    float* out = (float*)d_out;
    (void)in_sizes; (void)n_in; (void)out_size;

    cudaFuncSetAttribute(esn_cluster,
                         cudaFuncAttributeMaxDynamicSharedMemorySize, ESN_SMEM);
    cudaFuncSetAttribute(solve_kernel,
                         cudaFuncAttributeMaxDynamicSharedMemorySize, SOLVE_SMEM);

    esn_cluster<<<2 * B_DIM, 1024, ESN_SMEM>>>(x, Win, W1, W2);
    xtx_kernel<<<dim3(11, B_DIM), 256>>>(x);
    solve_kernel<<<B_DIM, SOLVE_T, SOLVE_SMEM>>>(out);
}

// round 12
// speedup vs baseline: 1.7000x; 1.0304x over previous
#include <cuda_runtime.h>
#include <math.h>
#include <stdint.h>

typedef unsigned long long ull;

#define H_DIM 64
#define W_DIM 64
#define B_DIM 64
#define R_DIM 128
#define D2    256
#define LPOS  (63*63)
#define NCHUNK ((LPOS + 15) / 16)        // 249

// scratch (device globals; no runtime allocation)
__device__ float g_S[(size_t)H_DIM * W_DIM * B_DIM * R_DIM];  // [cell][b][r]
__device__ float g_A[(size_t)B_DIM * D2 * D2];
__device__ float g_y[(size_t)B_DIM * D2];

// ---------------------------------------------------------------------------
// packed fp32x2 + cluster helpers
// ---------------------------------------------------------------------------
__device__ __forceinline__ ull ffma2(ull a, ull b, ull c)
{
    ull d;
    asm("fma.rn.f32x2 %0, %1, %2, %3;" : "=l"(d) : "l"(a), "l"(b), "l"(c));
    return d;
}
__device__ __forceinline__ ull fadd2(ull a, ull b)
{
    ull d;
    asm("add.rn.f32x2 %0, %1, %2;" : "=l"(d) : "l"(a), "l"(b));
    return d;
}
__device__ __forceinline__ float2 unpack2(ull v)
{
    float2 r;
    asm("mov.b64 {%0, %1}, %2;" : "=f"(r.x), "=f"(r.y) : "l"(v));
    return r;
}
__device__ __forceinline__ ull pack2(float a, float b)
{
    ull d;
    asm("mov.b64 %0, {%1, %2};" : "=l"(d) : "f"(a), "f"(b));
    return d;
}
__device__ __forceinline__ uint32_t smem_u32(const void* p)
{
    uint32_t a;
    asm("{ .reg .u64 t; cvta.to.shared.u64 t, %1; cvt.u32.u64 %0, t; }"
        : "=r"(a) : "l"(p));
    return a;
}
__device__ __forceinline__ void st_cluster_b32(uint32_t addr, float v)
{
    asm volatile("st.shared::cluster.b32 [%0], %1;" :: "r"(addr), "f"(v) : "memory");
}
#define CLUSTER_SYNC() do { \
    asm volatile("barrier.cluster.arrive.aligned;" ::: "memory"); \
    asm volatile("barrier.cluster.wait.aligned;"   ::: "memory"); \
} while (0)

// fast tanh: (1-e)/(1+e), e = exp(-2|z|); abs err ~1e-6, well inside budget.
__device__ __forceinline__ float fast_tanhf(float z)
{
    const float a = fabsf(z);
    const float e = __expf(-2.0f * a);
    const float r = __fdividef(1.0f - e, 1.0f + e);
    return copysignf(r, z);
}

// ---------------------------------------------------------------------------
// Kernel 1: ESN recurrence (FROZEN -- measured at structural floor: 885us,
// fma=33% == rt-3 issue occupancy + reduction crossbar + barriers).
// ---------------------------------------------------------------------------
#define CCH 32
#define ESN_BUF_FLOATS (65 * 128)
#define ESN_BUF_BYTES  (ESN_BUF_FLOATS * 4)                  // 33280
#define ESN_SMEM (2 * ESN_BUF_BYTES + CCH * 8 * 64 * 8)      // 66560 + 131072

__global__ __launch_bounds__(1024, 1) __cluster_dims__(2, 1, 1)
void esn_cluster(const float* __restrict__ x, const float* __restrict__ Win,
                 const float* __restrict__ W1, const float* __restrict__ W2)
{
    extern __shared__ float sm[];
    float* buf0 = sm;                          // [65][128] diag states
    float* buf1 = sm + ESN_BUF_FLOATS;
    ull*   red  = (ull*)(sm + 2 * ESN_BUF_FLOATS);   // [32][8][64]

    uint32_t rank;
    asm("mov.u32 %0, %%cluster_ctarank;" : "=r"(rank));
    const int b  = blockIdx.x >> 1;
    const int t  = threadIdx.x;
    const int g  = t >> 7;                     // 0..7
    const int subcell = (t >> 6) & 1;
    const int r  = t & 63;

    const int rbase = (int)(rank << 6);
    const int rcol  = rbase + r;
    const int kloc  = (g & 3) << 5;            // 0,32,64,96 within the matrix

    const float* Wsrc = (g < 4) ? W1 : W2;
    ull wreg[16];
#pragma unroll
    for (int j = 0; j < 16; j++) {
        const int k = kloc + 2 * j;
        wreg[j] = pack2(Wsrc[k * R_DIM + rcol], Wsrc[(k + 1) * R_DIM + rcol]);
    }
    const float winr = Win[rcol];
    const float* xb = x + ((size_t)b << 12);

    const uint32_t my_base = smem_u32(sm);
    uint32_t peer_base;
    asm("mapa.shared::cluster.u32 %0, %1, %2;"
        : "=r"(peer_base) : "r"(my_base), "r"(rank ^ 1u));

    // zero both diagonal buffers (zero slots double as boundary guards)
    {
        float4* z = (float4*)sm;
        for (int u = t; u < (2 * ESN_BUF_FLOATS) / 4; u += 1024)
            z[u] = make_float4(0.f, 0.f, 0.f, 0.f);
    }
    __syncthreads();
    CLUSTER_SYNC();   // peer zeroing done before our DSMEM stores can land

    for (int d = 0; d < H_DIM + W_DIM - 1; d++) {
        const int hmin = (d > 63) ? d - 63 : 0;
        const int hmax = (d < 63) ? d : 63;
        float* prev = (d & 1) ? buf0 : buf1;
        float* cur  = (d & 1) ? buf1 : buf0;
        const uint32_t cur_off = (d & 1) ? (uint32_t)ESN_BUF_BYTES : 0u;

        for (int c0 = hmin; c0 <= hmax; c0 += CCH) {
            const int nc = (hmax - c0 + 1 < CCH) ? (hmax - c0 + 1) : CCH;

            // ---- phase 1: k-packed partial dot products ----
#pragma unroll 1
            for (int pass = 0; pass < 16; pass++) {
                const int ci = (pass << 1) | subcell;
                if (ci >= nc) break;           // ci monotone in pass
                const int h = c0 + ci;
                const int slot = (g < 4) ? (h + 1) : h;
                const ulonglong2* src =
                    (const ulonglong2*)(prev + slot * 128 + kloc);
                ull a0 = 0ull, a1 = 0ull;
#pragma unroll
                for (int i = 0; i < 8; i++) {
                    const ulonglong2 s = src[i];       // 2x (s_2k, s_2k+1)
                    a0 = ffma2(s.x, wreg[2 * i],     a0);
                    a1 = ffma2(s.y, wreg[2 * i + 1], a1);
                }
                red[((ci << 3) + g) * 64 + r] = fadd2(a0, a1);
            }
            __syncthreads();

            // ---- phase 2: one (cell, r) output per thread, 2 reps ----
#pragma unroll 1
            for (int rep = 0; rep < 2; rep++) {
                const int ci = (t >> 6) + (rep << 4);
                if (ci < nc) {
                    const int h = c0 + ci;
                    const int w = d - h;
                    const ull* rr = red + (ci << 9) + r;
                    ull s0 = rr[0],       s1 = rr[64];
                    ull s2 = rr[2 * 64],  s3 = rr[3 * 64];
                    s0 = fadd2(s0, rr[4 * 64]);
                    s1 = fadd2(s1, rr[5 * 64]);
                    s2 = fadd2(s2, rr[6 * 64]);
                    s3 = fadd2(s3, rr[7 * 64]);
                    const float2 v = unpack2(fadd2(fadd2(s0, s1), fadd2(s2, s3)));
                    const float xv = __ldg(xb + (h << 6) + w);
                    const float o = fast_tanhf(fmaf(xv, winr, v.x + v.y));
                    const int idx = (h + 1) * 128 + rcol;
                    cur[idx] = o;
                    st_cluster_b32(peer_base + cur_off + (uint32_t)idx * 4u, o);
                    g_S[((size_t)(((h << 6) + w) << 6) + b) * R_DIM + rcol] = o;
                }
            }
            __syncthreads();
        }
        CLUSTER_SYNC();   // publish DSMEM half-states before next diagonal
    }
}

// ---------------------------------------------------------------------------
// Kernel 2: XtX (symmetric, f32x2, register-dup B) + FUSED Xty.
// DOUBLE-BUFFERED staging: prefetch chunk c+1 into registers during compute
// of chunk c, store into the alternate smem buffer, ONE sync per chunk.
// grid = (11, 64): p=0..9 -> XtX tile-pairs, p=10 -> Xty for that batch.
// ---------------------------------------------------------------------------
__global__ __launch_bounds__(256) void xtx_kernel(const float* __restrict__ x)
{
    const int b = blockIdx.y;
    const int p = blockIdx.x;
    const int t = threadIdx.x;

    if (p == 10) {
        // ---- fused Xty, 4 independent accumulators ----
        const int half = t >> 7;
        const int r    = t & 127;
        float a0 = 0.f, a1 = 0.f, a2 = 0.f, a3 = 0.f;
#pragma unroll 1
        for (int i = 0; i < 63; i++) {
            const float* tgt_row = x + ((size_t)b << 12) + (i + 1) * W_DIM + 1;
            const int rowc = (half == 0) ? ((i + 1) * W_DIM) : (i * W_DIM + 1);
#pragma unroll 4
            for (int j = 0; j < 60; j += 4) {
                a0 = fmaf(g_S[((size_t)(rowc + j + 0) * B_DIM + b) * R_DIM + r], tgt_row[j + 0], a0);
                a1 = fmaf(g_S[((size_t)(rowc + j + 1) * B_DIM + b) * R_DIM + r], tgt_row[j + 1], a1);
                a2 = fmaf(g_S[((size_t)(rowc + j + 2) * B_DIM + b) * R_DIM + r], tgt_row[j + 2], a2);
                a3 = fmaf(g_S[((size_t)(rowc + j + 3) * B_DIM + b) * R_DIM + r], tgt_row[j + 3], a3);
            }
            a0 = fmaf(g_S[((size_t)(rowc + 60) * B_DIM + b) * R_DIM + r], tgt_row[60], a0);
            a1 = fmaf(g_S[((size_t)(rowc + 61) * B_DIM + b) * R_DIM + r], tgt_row[61], a1);
            a2 = fmaf(g_S[((size_t)(rowc + 62) * B_DIM + b) * R_DIM + r], tgt_row[62], a2);
        }
        g_y[(size_t)b * D2 + t] = (a0 + a1) + (a2 + a3);
        return;
    }

    const int ti = (p < 4) ? 0 : (p < 7) ? 1 : (p < 9) ? 2 : 3;
    const int tbase = (ti == 0) ? 0 : (ti == 1) ? 4 : (ti == 2) ? 7 : 9;
    const int tj = ti + (p - tbase);

    const int di0 = (t & 15) << 2;
    const int dj0 = (t >> 4) << 2;
    const int lr = t >> 4;
    const int qq = t & 15;

    __shared__ float sA[2][16][64];
    __shared__ float sB[2][16][64];

    const int offA = (ti & 1) << 6;
    const int offB = (tj & 1) << 6;

    // chunk loader: (va, vb) for position l = c*16 + lr
    float4 va, vb;
    auto load_chunk = [&](int c) {
        va = make_float4(0.f, 0.f, 0.f, 0.f);
        vb = make_float4(0.f, 0.f, 0.f, 0.f);
        const int l = c * 16 + lr;
        if (l < LPOS) {
            const int i = l / 63;
            const int j = l - i * 63;
            const int cellA = (ti < 2) ? ((i + 1) * W_DIM + j) : (i * W_DIM + j + 1);
            const int cellB = (tj < 2) ? ((i + 1) * W_DIM + j) : (i * W_DIM + j + 1);
            va = *(const float4*)(g_S + (((size_t)cellA << 6) + b) * R_DIM + offA + (qq << 2));
            vb = *(const float4*)(g_S + (((size_t)cellB << 6) + b) * R_DIM + offB + (qq << 2));
        }
    };

    ull acc[2][4];
#pragma unroll
    for (int pp = 0; pp < 2; pp++)
#pragma unroll
        for (int j = 0; j < 4; j++) acc[pp][j] = 0ull;

    // prologue: chunk 0 into buffer 0
    load_chunk(0);
    *(float4*)&sA[0][lr][qq << 2] = va;
    *(float4*)&sB[0][lr][qq << 2] = vb;
    __syncthreads();

#pragma unroll 1
    for (int c = 0; c < NCHUNK; c++) {
        const int cur = c & 1;

        // prefetch chunk c+1 (long-latency LDG overlapped with compute)
        const bool have_next = (c + 1 < NCHUNK);
        if (have_next) load_chunk(c + 1);

#pragma unroll
        for (int l2 = 0; l2 < 16; l2++) {
            const ulonglong2 av = *(const ulonglong2*)&sA[cur][l2][di0];
            const float4 bv = *(const float4*)&sB[cur][l2][dj0];
            const ull b0 = pack2(bv.x, bv.x);
            const ull b1 = pack2(bv.y, bv.y);
            const ull b2 = pack2(bv.z, bv.z);
            const ull b3 = pack2(bv.w, bv.w);
            acc[0][0] = ffma2(av.x, b0, acc[0][0]);
            acc[1][0] = ffma2(av.y, b0, acc[1][0]);
            acc[0][1] = ffma2(av.x, b1, acc[0][1]);
            acc[1][1] = ffma2(av.y, b1, acc[1][1]);
            acc[0][2] = ffma2(av.x, b2, acc[0][2]);
            acc[1][2] = ffma2(av.y, b2, acc[1][2]);
            acc[0][3] = ffma2(av.x, b3, acc[0][3]);
            acc[1][3] = ffma2(av.y, b3, acc[1][3]);
        }

        if (have_next) {
            // alternate buffer was last read in chunk c-1; every thread passed
            // the sync at the end of chunk c-1, so overwrite is safe pre-sync.
            *(float4*)&sA[cur ^ 1][lr][qq << 2] = va;
            *(float4*)&sB[cur ^ 1][lr][qq << 2] = vb;
        }
        __syncthreads();
    }

    float cc[4][4];
#pragma unroll
    for (int pp = 0; pp < 2; pp++)
#pragma unroll
        for (int j = 0; j < 4; j++) {
            const float2 v = unpack2(acc[pp][j]);
            cc[2 * pp][j] = v.x;
            cc[2 * pp + 1][j] = v.y;
        }

    const size_t base = (size_t)b * D2 * D2;
#pragma unroll
    for (int ii = 0; ii < 4; ii++)
        *(float4*)(g_A + base + (size_t)(ti * 64 + di0 + ii) * D2 + tj * 64 + dj0) =
            make_float4(cc[ii][0], cc[ii][1], cc[ii][2], cc[ii][3]);
    if (ti != tj) {
#pragma unroll
        for (int jj = 0; jj < 4; jj++)
            *(float4*)(g_A + base + (size_t)(tj * 64 + dj0 + jj) * D2 + ti * 64 + di0) =
                make_float4(cc[0][jj], cc[1][jj], cc[2][jj], cc[3][jj]);
    }
}

// ---------------------------------------------------------------------------
// Kernel 3: blocked Cholesky solve (NB=32), 512 threads.  Diag-factor inner
// update now uses rectangular (a,m) indexing + predicate: no tri_row sqrt on
// the 256-step serial path.
// ---------------------------------------------------------------------------
#define SOLVE_T 512
#define PK_ELEMS (D2 * (D2 + 1) / 2)                 // 32896
#define LP_STRIDE 36
#define LP_FLOATS (224 * LP_STRIDE)                  // 8064
#define SOLVE_SMEM ((PK_ELEMS + LP_FLOATS + 4 * D2) * 4)

__device__ __forceinline__ int pkrow(int i) { return (i * (i + 1)) >> 1; }

__device__ __forceinline__ int tri_row(int e)
{
    int a = (int)((sqrtf(8.0f * (float)e + 1.0f) - 1.0f) * 0.5f);
    while (pkrow(a) > e) a--;
    while (pkrow(a + 1) <= e) a++;
    return a;
}

__global__ __launch_bounds__(SOLVE_T) void solve_kernel(float* __restrict__ out)
{
    extern __shared__ float smref[];
    float* P   = smref;
    float* Lp  = smref + PK_ELEMS;
    float* dgv = Lp + LP_FLOATS;
    float* riv = dgv + D2;
    float* zz  = riv + D2;
    float* xs  = zz + D2;

    const int b = blockIdx.x;
    const int t = threadIdx.x;
    const float* A = g_A + (size_t)b * D2 * D2;

    // load packed lower triangle + ridge
#pragma unroll 1
    for (int i = 0; i < D2; i++) {
        const int base = pkrow(i);
        for (int j = t; j <= i; j += SOLVE_T)
            P[base + j] = A[(size_t)i * D2 + j] + ((j == i) ? 0.9f : 0.0f);
    }
    if (t < D2) zz[t] = g_y[(size_t)b * D2 + t];
    __syncthreads();

#pragma unroll 1
    for (int kb = 0; kb < 8; kb++) {
        const int base = kb * 32;

        // ---- factor 32x32 diagonal block ----
#pragma unroll 1
        for (int j = 0; j < 32; j++) {
            const int jj = base + j;
            const float dj = sqrtf(P[pkrow(jj) + jj]);   // stable since last sync
            const float ri = 1.0f / dj;
            if (t == 0) { dgv[jj] = dj; riv[jj] = ri; }
            if (t > j && t < 32) P[pkrow(base + t) + jj] *= ri;
            __syncthreads();
            const int rem = 31 - j;
            // rectangular: a = e>>5 in [0,rem), m = e&31, predicate m<=a
            for (int e = t; e < (rem << 5); e += SOLVE_T) {
                const int a = e >> 5;
                const int mloc = e & 31;
                if (mloc <= a) {
                    const int i = base + j + 1 + a;
                    const int m = base + j + 1 + mloc;
                    P[pkrow(i) + m] -= P[pkrow(i) + jj] * P[pkrow(m) + jj];
                }
            }
            __syncthreads();
        }

        const int rows = D2 - base - 32;
        if (rows > 0) {
            // ---- panel triangular solve: one row per thread, no syncs ----
            if (t < rows) {
                const int gi = base + 32 + t;
                const int rb = pkrow(gi) + base;
                float v[32];
#pragma unroll
                for (int m = 0; m < 32; m++) v[m] = P[rb + m];
#pragma unroll
                for (int j = 0; j < 32; j++) {
                    float s = v[j];
                    const int lb = pkrow(base + j) + base;
#pragma unroll
                    for (int m = 0; m < 32; m++) {
                        if (m < j) s -= v[m] * P[lb + m];
                    }
                    v[j] = s * riv[base + j];
                }
#pragma unroll
                for (int m = 0; m < 32; m++) {
                    P[rb + m] = v[m];
                    Lp[t * LP_STRIDE + m] = v[m];
                }
            }
            __syncthreads();

            // ---- trailing update: A22 -= L21 L21^T ----
            const int cnt = (rows * (rows + 1)) >> 1;
            for (int e = t; e < cnt; e += SOLVE_T) {
                const int a = tri_row(e);
                const int jloc = e - pkrow(a);
                const float4* ra = (const float4*)(Lp + a * LP_STRIDE);
                const float4* rj = (const float4*)(Lp + jloc * LP_STRIDE);
                float s = 0.0f;
#pragma unroll
                for (int mm = 0; mm < 8; mm++) {
                    const float4 u4 = ra[mm];
                    const float4 v4 = rj[mm];
                    s = fmaf(u4.x, v4.x, s);
                    s = fmaf(u4.y, v4.y, s);
                    s = fmaf(u4.z, v4.z, s);
                    s = fmaf(u4.w, v4.w, s);
                }
                const int gi = base + 32 + a;
                const int gj = base + 32 + jloc;
                P[pkrow(gi) + gj] -= s;
            }
            __syncthreads();
        }
    }

    // forward solve L z = y
#pragma unroll 1
    for (int k = 0; k < D2; k++) {
        __syncthreads();
        const float xk = zz[k] * riv[k];
        if (t == k) xs[k] = xk;
        if (t > k && t < D2) zz[t] -= P[pkrow(t) + k] * xk;
    }
    __syncthreads();

    // backward solve L^T w = z
#pragma unroll 1
    for (int k = D2 - 1; k >= 0; k--) {
        __syncthreads();
        const float wk = xs[k] * riv[k];
        if (t == k) out[(size_t)b * D2 + k] = wk;
        if (t < k)  xs[t] -= P[pkrow(k) + t] * wk;
    }
}

// ---------------------------------------------------------------------------
// kernel_launch
// ---------------------------------------------------------------------------
extern "C" void kernel_launch(void* const* d_in, const int* in_sizes, int n_in,
                              void* d_out, int out_size)
{
    const float* x   = (const float*)d_in[0];
    const float* Win = (const float*)d_in[1];
    const float* W1  = (const float*)d_in[2];
    const float* W2  = (const float*)d_in[3];
    float* out = (float*)d_out;
    (void)in_sizes; (void)n_in; (void)out_size;

    cudaFuncSetAttribute(esn_cluster,
                         cudaFuncAttributeMaxDynamicSharedMemorySize, ESN_SMEM);
    cudaFuncSetAttribute(solve_kernel,
                         cudaFuncAttributeMaxDynamicSharedMemorySize, SOLVE_SMEM);

    esn_cluster<<<2 * B_DIM, 1024, ESN_SMEM>>>(x, Win, W1, W2);
    xtx_kernel<<<dim3(11, B_DIM), 256>>>(x);
    solve_kernel<<<B_DIM, SOLVE_T, SOLVE_SMEM>>>(out);
}